// round 13
// baseline (speedup 1.0000x reference)
#include <cuda_runtime.h>
#include <cuda_fp16.h>
#include <stdint.h>

#define B_   4
#define S_   2048
#define H_   16
#define D_   64
#define HID  1024
#define M_   (B_*S_)            // 8192
#define QSCALE 0.1803368801111f // 0.125 * log2(e)  (folded into q)

// ---------------- scratch (device globals; no cudaMalloc allowed) ----------
__device__ __align__(16) __half g_x[(size_t)M_*HID];
__device__ __align__(16) __half g_wq[HID*HID], g_wk[HID*HID], g_wv[HID*HID], g_wo[HID*HID];
__device__ __align__(16) __half g_q[(size_t)M_*HID], g_k[(size_t)M_*HID], g_v[(size_t)M_*HID]; // [bh][s][d]
__device__ __align__(16) __half g_a[(size_t)M_*HID];  // attn out [b*S+s][h*64+d]

// ---------------- PTX helpers ----------------------------------------------
__device__ __forceinline__ uint32_t smem_u32(const void* p) {
    return (uint32_t)__cvta_generic_to_shared(p);
}
#define CP16(dst, src) asm volatile("cp.async.cg.shared.global [%0], [%1], 16;\n" :: "r"(dst), "l"(src))
#define CP_COMMIT()    asm volatile("cp.async.commit_group;\n")
#define CP_WAIT1()     asm volatile("cp.async.wait_group 1;\n")

#define LDSM_X4(r0,r1,r2,r3,addr) \
    asm volatile("ldmatrix.sync.aligned.m8n8.x4.shared.b16 {%0,%1,%2,%3}, [%4];\n" \
        : "=r"(r0),"=r"(r1),"=r"(r2),"=r"(r3) : "r"(addr))
#define LDSM_X4_T(r0,r1,r2,r3,addr) \
    asm volatile("ldmatrix.sync.aligned.m8n8.x4.trans.shared.b16 {%0,%1,%2,%3}, [%4];\n" \
        : "=r"(r0),"=r"(r1),"=r"(r2),"=r"(r3) : "r"(addr))

__device__ __forceinline__ void mma16816(float* c, uint32_t a0, uint32_t a1,
                                         uint32_t a2, uint32_t a3,
                                         uint32_t b0, uint32_t b1) {
    asm volatile("mma.sync.aligned.m16n8k16.row.col.f32.f16.f16.f32 "
                 "{%0,%1,%2,%3}, {%4,%5,%6,%7}, {%8,%9}, {%0,%1,%2,%3};\n"
                 : "+f"(c[0]), "+f"(c[1]), "+f"(c[2]), "+f"(c[3])
                 : "r"(a0), "r"(a1), "r"(a2), "r"(a3), "r"(b0), "r"(b1));
}
__device__ __forceinline__ void mma16816_h(uint32_t* c, uint32_t a0, uint32_t a1,
                                           uint32_t a2, uint32_t a3,
                                           uint32_t b0, uint32_t b1) {
    asm volatile("mma.sync.aligned.m16n8k16.row.col.f16.f16.f16.f16 "
                 "{%0,%1}, {%2,%3,%4,%5}, {%6,%7}, {%0,%1};\n"
                 : "+r"(c[0]), "+r"(c[1])
                 : "r"(a0), "r"(a1), "r"(a2), "r"(a3), "r"(b0), "r"(b1));
}
__device__ __forceinline__ uint32_t ex2_f16x2(uint32_t h) {
    uint32_t p; asm("ex2.approx.f16x2 %0, %1;\n" : "=r"(p) : "r"(h)); return p;
}
__device__ __forceinline__ uint32_t h2pack(float a, float b) {
    __half2 h = __floats2half2_rn(a, b);
    return *reinterpret_cast<uint32_t*>(&h);
}
__device__ __forceinline__ uint32_t hadd2u(uint32_t a, uint32_t b) {
    __half2 r = __hadd2(*reinterpret_cast<__half2*>(&a), *reinterpret_cast<__half2*>(&b));
    return *reinterpret_cast<uint32_t*>(&r);
}
__device__ __forceinline__ uint32_t sw_off(int row, int chunk) {
    return (uint32_t)(row * 128 + ((chunk ^ (row & 7)) << 4));
}

// ---------------- fp32 -> fp16 converts --------------------------------------
__global__ void tohalf_w(const float* __restrict__ Wq, const float* __restrict__ Wk,
                         const float* __restrict__ Wv, const float* __restrict__ Wo)
{
    int j = blockIdx.x * blockDim.x + threadIdx.x;
    int w = j >> 18, idx = j & ((1 << 18) - 1);
    const float* src = w == 0 ? Wq  : w == 1 ? Wk  : w == 2 ? Wv  : Wo;
    __half*      dst = w == 0 ? g_wq : w == 1 ? g_wk : w == 2 ? g_wv : g_wo;
    float4 v = ((const float4*)src)[idx];
    uint2 o; o.x = h2pack(v.x, v.y); o.y = h2pack(v.z, v.w);
    ((uint2*)dst)[idx] = o;
}
__global__ void tohalf_x(const float* __restrict__ x, int half)
{
    int i = blockIdx.x * blockDim.x + threadIdx.x;
    int idx = i + half * (1 << 20);
    float4 v = ((const float4*)x)[idx];
    uint2 o; o.x = h2pack(v.x, v.y); o.y = h2pack(v.z, v.w);
    ((uint2*)g_x)[idx] = o;
}

// ---------------- GEMM: C = A @ W^T + b --------------------------------------
// CTA tile 64x128 (M x N), 128 threads / 4 warps (2m x 2n), warp tile 32x64.
// acc 64 regs -> ~120 total -> 3 CTAs/SM (3 warps/SMSP latency hiding).
// 3-stage cp.async pipeline, one __syncthreads per K-chunk.
#define GSTAGE  24576   // bytes per stage (A 8KB + W 16KB)
#define GSTAGES 3

template<int MODE>
__global__ __launch_bounds__(128, 3) void gemm_kernel(
    const float* __restrict__ b0p, const float* __restrict__ b1p,
    const float* __restrict__ b2p, float* __restrict__ Cout, int yoff)
{
    extern __shared__ char smem[];
    const uint32_t su = smem_u32(smem);
    const int tid = threadIdx.x, lane = tid & 31, wid = tid >> 5;
    const int wm = wid >> 1, wn = wid & 1;
    const int m0 = (blockIdx.y + yoff) * 64;

    const __half* A = (MODE == 0) ? g_x : g_a;
    const __half* W; const float* bias; int which, nloc0;
    if (MODE == 0) {
        which = blockIdx.x >> 3;
        nloc0 = (blockIdx.x & 7) * 128;
        W    = which == 0 ? g_wq : (which == 1 ? g_wk : g_wv);
        bias = which == 0 ? b0p  : (which == 1 ? b1p  : b2p);
    } else {
        which = 0; nloc0 = blockIdx.x * 128;
        W = g_wo; bias = b0p;
    }

    float acc[2][8][4];
#pragma unroll
    for (int mt = 0; mt < 2; mt++)
#pragma unroll
        for (int nt = 0; nt < 8; nt++)
#pragma unroll
            for (int r = 0; r < 4; r++) acc[mt][nt][r] = 0.f;

    auto load_stage = [&](int st, int k0) {
        uint32_t sb = su + st * GSTAGE;
        // A: 64 rows x 8 chunks = 512 units
#pragma unroll
        for (int i = 0; i < 4; i++) {
            int id = tid + i * 128;
            int row = id >> 3, ch = id & 7;
            CP16(sb + sw_off(row, ch), A + (size_t)(m0 + row) * HID + k0 + ch * 8);
        }
        // W: 128 rows x 8 chunks = 1024 units
#pragma unroll
        for (int i = 0; i < 8; i++) {
            int id = tid + i * 128;
            int row = id >> 3, ch = id & 7;
            CP16(sb + 8192 + sw_off(row, ch), W + (size_t)(nloc0 + row) * HID + k0 + ch * 8);
        }
        CP_COMMIT();
    };

    load_stage(0, 0);
    load_stage(1, 64);
    CP_WAIT1();
    __syncthreads();

    for (int it = 0; it < 16; it++) {
        uint32_t sA = su + (it % GSTAGES) * GSTAGE;
        uint32_t sB = sA + 8192;

#pragma unroll
        for (int ks = 0; ks < 4; ks++) {
            uint32_t a[2][4];
#pragma unroll
            for (int mt = 0; mt < 2; mt++) {
                int row = wm * 32 + mt * 16 + (lane & 15);
                int ch  = ks * 2 + (lane >> 4);
                LDSM_X4(a[mt][0], a[mt][1], a[mt][2], a[mt][3], sA + sw_off(row, ch));
            }
            uint32_t b[4][4];
#pragma unroll
            for (int pr = 0; pr < 4; pr++) {
                int row = wn * 64 + pr * 16 + (lane & 7) + 8 * (lane >> 4);
                int ch  = ks * 2 + ((lane >> 3) & 1);
                LDSM_X4(b[pr][0], b[pr][1], b[pr][2], b[pr][3], sB + sw_off(row, ch));
            }
#pragma unroll
            for (int mt = 0; mt < 2; mt++)
#pragma unroll
                for (int nt = 0; nt < 8; nt++) {
                    int pr = nt >> 1, ix = (nt & 1) * 2;
                    mma16816(acc[mt][nt], a[mt][0], a[mt][1], a[mt][2], a[mt][3],
                             b[pr][ix], b[pr][ix + 1]);
                }
        }

        if (it + 2 < 16) load_stage((it + 2) % GSTAGES, (it + 2) * 64);
        else             CP_COMMIT();
        CP_WAIT1();
        __syncthreads();
    }

    const int gr = lane >> 2, gc2 = (lane & 3) * 2;
#pragma unroll
    for (int mt = 0; mt < 2; mt++) {
#pragma unroll
        for (int nt = 0; nt < 8; nt++) {
            int c = nloc0 + wn * 64 + nt * 8 + gc2;
            float bi0 = bias[c], bi1 = bias[c + 1];
#pragma unroll
            for (int r = 0; r < 2; r++) {
                int m = m0 + wm * 32 + mt * 16 + gr + r * 8;
                float v0 = acc[mt][nt][r * 2 + 0] + bi0;
                float v1 = acc[mt][nt][r * 2 + 1] + bi1;
                if (MODE == 0) {
                    if (which == 0) { v0 *= QSCALE; v1 *= QSCALE; }
                    __half* dst = which == 0 ? g_q : (which == 1 ? g_k : g_v);
                    int b = m >> 11, s = m & (S_ - 1);
                    int h = c >> 6, d = c & 63;
                    __half2 hv = __floats2half2_rn(v0, v1);
                    *(__half2*)&dst[(((size_t)(b * H_ + h)) * S_ + s) * D_ + d] = hv;
                } else {
                    float2 f2 = make_float2(v0, v1);
                    *(float2*)&Cout[(size_t)m * HID + c] = f2;
                }
            }
        }
    }
}

// ---------------- flash attention (unchanged) --------------------------------
#define ASTAGE 16384

__global__ __launch_bounds__(256, 2) void attn_kernel(int bhoff)
{
    extern __shared__ char smem[];
    const uint32_t su  = smem_u32(smem);
    const uint32_t sKV = su + 16384;
    const int tid = threadIdx.x, lane = tid & 31, wid = tid >> 5;
    const int qt = blockIdx.x, bh = blockIdx.y + bhoff;
    const size_t qbase  = ((size_t)bh * S_ + qt * 128) * D_;
    const size_t kvbase = (size_t)bh * S_ * D_;

#pragma unroll
    for (int i = 0; i < 4; i++) {
        int id = tid + i * 256;
        int row = id >> 3, ch = id & 7;
        CP16(su + sw_off(row, ch), g_q + qbase + (size_t)row * 64 + ch * 8);
    }
    CP_COMMIT();

    auto load_kv = [&](int st, int kt) {
        const __half* kp = g_k + kvbase + (size_t)kt * 64 * 64;
        const __half* vp = g_v + kvbase + (size_t)kt * 64 * 64;
        uint32_t sb = sKV + st * ASTAGE;
#pragma unroll
        for (int i = 0; i < 2; i++) {
            int id = tid + i * 256;
            int row = id >> 3, ch = id & 7;
            uint32_t off = sw_off(row, ch);
            CP16(sb + off,        kp + (size_t)row * 64 + ch * 8);
            CP16(sb + 8192 + off, vp + (size_t)row * 64 + ch * 8);
        }
        CP_COMMIT();
    };
    load_kv(0, 0);
    load_kv(1, 1);

    CP_WAIT1();
    __syncthreads();

    uint32_t qf[4][4];
#pragma unroll
    for (int ks = 0; ks < 4; ks++) {
        int row = wid * 16 + (lane & 15);
        int ch  = ks * 2 + (lane >> 4);
        LDSM_X4(qf[ks][0], qf[ks][1], qf[ks][2], qf[ks][3], su + sw_off(row, ch));
    }

    float oa[8][4];
#pragma unroll
    for (int nt = 0; nt < 8; nt++)
#pragma unroll
        for (int r = 0; r < 4; r++) oa[nt][r] = 0.f;
    float rs0 = 0.f, rs1 = 0.f;

    for (int kt = 0; kt < 32; kt++) {
        const uint32_t kb = sKV + (kt % 3) * ASTAGE;
        const uint32_t vb = kb + 8192;

        uint32_t sch[8][2];
#pragma unroll
        for (int nt = 0; nt < 8; nt++) { sch[nt][0] = 0u; sch[nt][1] = 0u; }
#pragma unroll
        for (int ks = 0; ks < 4; ks++) {
#pragma unroll
            for (int pr = 0; pr < 4; pr++) {
                uint32_t bk0, bk1, bk2, bk3;
                int row = pr * 16 + (lane & 7) + 8 * (lane >> 4);
                int ch  = ks * 2 + ((lane >> 3) & 1);
                LDSM_X4(bk0, bk1, bk2, bk3, kb + sw_off(row, ch));
                mma16816_h(sch[pr * 2 + 0], qf[ks][0], qf[ks][1], qf[ks][2], qf[ks][3], bk0, bk1);
                mma16816_h(sch[pr * 2 + 1], qf[ks][0], qf[ks][1], qf[ks][2], qf[ks][3], bk2, bk3);
            }
        }

        uint32_t pa[4][4];
        uint32_t hs0 = 0, hs1 = 0;
#pragma unroll
        for (int ks = 0; ks < 4; ks++) {
            uint32_t p00 = ex2_f16x2(sch[2 * ks + 0][0]);
            uint32_t p01 = ex2_f16x2(sch[2 * ks + 0][1]);
            uint32_t p10 = ex2_f16x2(sch[2 * ks + 1][0]);
            uint32_t p11 = ex2_f16x2(sch[2 * ks + 1][1]);
            pa[ks][0] = p00; pa[ks][1] = p01; pa[ks][2] = p10; pa[ks][3] = p11;
            hs0 = hadd2u(hadd2u(hs0, p00), p10);
            hs1 = hadd2u(hadd2u(hs1, p01), p11);
        }
        {
            float2 f0 = __half22float2(*reinterpret_cast<__half2*>(&hs0));
            float2 f1 = __half22float2(*reinterpret_cast<__half2*>(&hs1));
            rs0 += f0.x + f0.y;
            rs1 += f1.x + f1.y;
        }

#pragma unroll
        for (int ks = 0; ks < 4; ks++) {
#pragma unroll
            for (int pr = 0; pr < 4; pr++) {
                uint32_t bv0, bv1, bv2, bv3;
                int row = ks * 16 + (lane & 15);
                int ch  = pr * 2 + (lane >> 4);
                LDSM_X4_T(bv0, bv1, bv2, bv3, vb + sw_off(row, ch));
                mma16816(oa[pr * 2 + 0], pa[ks][0], pa[ks][1], pa[ks][2], pa[ks][3], bv0, bv1);
                mma16816(oa[pr * 2 + 1], pa[ks][0], pa[ks][1], pa[ks][2], pa[ks][3], bv2, bv3);
            }
        }

        if (kt + 2 < 32) load_kv((kt + 2) % 3, kt + 2);
        else             CP_COMMIT();
        CP_WAIT1();
        __syncthreads();
    }

    rs0 += __shfl_xor_sync(0xffffffffu, rs0, 1);
    rs0 += __shfl_xor_sync(0xffffffffu, rs0, 2);
    rs1 += __shfl_xor_sync(0xffffffffu, rs1, 1);
    rs1 += __shfl_xor_sync(0xffffffffu, rs1, 2);

    const int b = bh >> 4, h = bh & 15;
    const float inv0 = 1.f / rs0, inv1 = 1.f / rs1;
    const int gr = lane >> 2, gc2 = (lane & 3) * 2;
#pragma unroll
    for (int nt = 0; nt < 8; nt++) {
        int d = nt * 8 + gc2;
        int col = h * 64 + d;
#pragma unroll
        for (int r = 0; r < 2; r++) {
            int sG = qt * 128 + wid * 16 + gr + r * 8;
            size_t idx = ((size_t)(b * S_ + sG)) * HID + col;
            float v0 = oa[nt][r * 2 + 0] * (r ? inv1 : inv0);
            float v1 = oa[nt][r * 2 + 1] * (r ? inv1 : inv0);
            *(__half2*)&g_a[idx] = __floats2half2_rn(v0, v1);
        }
    }
}

// ---------------- streams/events: created at program load -------------------
struct StreamBundle {
    cudaStream_t s1 = nullptr, s2 = nullptr;
    cudaEvent_t  eFork = nullptr, eW = nullptr, eX0 = nullptr, eJoin = nullptr;
    bool ok = false;
    StreamBundle() { init(); }
    void init() {
        if (ok) return;
        if (cudaStreamCreateWithFlags(&s1, cudaStreamNonBlocking) != cudaSuccess) return;
        if (cudaStreamCreateWithFlags(&s2, cudaStreamNonBlocking) != cudaSuccess) return;
        if (cudaEventCreateWithFlags(&eFork, cudaEventDisableTiming) != cudaSuccess) return;
        if (cudaEventCreateWithFlags(&eW,    cudaEventDisableTiming) != cudaSuccess) return;
        if (cudaEventCreateWithFlags(&eX0,   cudaEventDisableTiming) != cudaSuccess) return;
        if (cudaEventCreateWithFlags(&eJoin, cudaEventDisableTiming) != cudaSuccess) return;
        ok = true;
    }
};
static StreamBundle g_sb;

// ---------------------------------------------------------------------------
extern "C" void kernel_launch(void* const* d_in, const int* in_sizes, int n_in,
                              void* d_out, int out_size)
{
    const float* x  = (const float*)d_in[0];
    const float* Wq = (const float*)d_in[1];
    const float* bq = (const float*)d_in[2];
    const float* Wk = (const float*)d_in[3];
    const float* bk = (const float*)d_in[4];
    const float* Wv = (const float*)d_in[5];
    const float* bv = (const float*)d_in[6];
    const float* Wo = (const float*)d_in[7];
    const float* bo = (const float*)d_in[8];
    float* out = (float*)d_out;

    static bool attr_done = false;
    if (!attr_done) {
        cudaFuncSetAttribute(gemm_kernel<0>, cudaFuncAttributeMaxDynamicSharedMemorySize, GSTAGES * GSTAGE);
        cudaFuncSetAttribute(gemm_kernel<1>, cudaFuncAttributeMaxDynamicSharedMemorySize, GSTAGES * GSTAGE);
        cudaFuncSetAttribute(attn_kernel,    cudaFuncAttributeMaxDynamicSharedMemorySize, 65536);
        attr_done = true;
    }
    g_sb.init();

    const cudaStream_t s0 = 0;
    const bool fork = g_sb.ok;
    const cudaStream_t s1 = fork ? g_sb.s1 : s0;
    const cudaStream_t s2 = fork ? g_sb.s2 : s0;

    if (fork) {
        cudaEventRecord(g_sb.eFork, s0);
        cudaStreamWaitEvent(s1, g_sb.eFork, 0);
        cudaStreamWaitEvent(s2, g_sb.eFork, 0);
    }

    tohalf_w<<<(4 * (1 << 18)) / 256, 256, 0, s0>>>(Wq, Wk, Wv, Wo);
    if (fork) cudaEventRecord(g_sb.eW, s0);

    tohalf_x<<<(1 << 20) / 256, 256, 0, s2>>>(x, 0);
    if (fork) {
        cudaEventRecord(g_sb.eX0, s2);
        cudaStreamWaitEvent(s0, g_sb.eX0, 0);
    }

    tohalf_x<<<(1 << 20) / 256, 256, 0, s1>>>(x, 1);
    if (fork) cudaStreamWaitEvent(s1, g_sb.eW, 0);

    // chain 1 (batches 2,3) on s1 — M blocks of 64 rows: 4096/64 = 64 per chain
    {
        dim3 g1(24, 64);
        gemm_kernel<0><<<g1, 128, GSTAGES * GSTAGE, s1>>>(bq, bk, bv, nullptr, 64);
        dim3 g2(16, 32);
        attn_kernel<<<g2, 256, 65536, s1>>>(32);
        dim3 g3(8, 64);
        gemm_kernel<1><<<g3, 128, GSTAGES * GSTAGE, s1>>>(bo, nullptr, nullptr, out, 64);
    }

    // chain 0 (batches 0,1) on s0
    {
        dim3 g1(24, 64);
        gemm_kernel<0><<<g1, 128, GSTAGES * GSTAGE, s0>>>(bq, bk, bv, nullptr, 0);
        dim3 g2(16, 32);
        attn_kernel<<<g2, 256, 65536, s0>>>(0);
        dim3 g3(8, 64);
        gemm_kernel<1><<<g3, 128, GSTAGES * GSTAGE, s0>>>(bo, nullptr, nullptr, out, 0);
    }

    if (fork) {
        cudaEventRecord(g_sb.eJoin, s1);
        cudaStreamWaitEvent(s0, g_sb.eJoin, 0);
    }
}

// round 14
// speedup vs baseline: 1.0006x; 1.0006x over previous
#include <cuda_runtime.h>
#include <cuda_fp16.h>
#include <stdint.h>

#define B_   4
#define S_   2048
#define H_   16
#define D_   64
#define HID  1024
#define M_   (B_*S_)            // 8192
#define QSCALE 0.1803368801111f // 0.125 * log2(e)  (folded into q)

// ---------------- scratch (device globals; no cudaMalloc allowed) ----------
__device__ __align__(16) __half g_x[(size_t)M_*HID];
__device__ __align__(16) __half g_wq[HID*HID], g_wk[HID*HID], g_wv[HID*HID], g_wo[HID*HID];
__device__ __align__(16) __half g_q[(size_t)M_*HID], g_k[(size_t)M_*HID], g_v[(size_t)M_*HID]; // [bh][s][d]
__device__ __align__(16) __half g_a[(size_t)M_*HID];  // attn out [b*S+s][h*64+d]

// ---------------- PTX helpers ----------------------------------------------
__device__ __forceinline__ uint32_t smem_u32(const void* p) {
    return (uint32_t)__cvta_generic_to_shared(p);
}
#define CP16(dst, src) asm volatile("cp.async.cg.shared.global [%0], [%1], 16;\n" :: "r"(dst), "l"(src))
#define CP_COMMIT()    asm volatile("cp.async.commit_group;\n")
#define CP_WAIT1()     asm volatile("cp.async.wait_group 1;\n")

#define LDSM_X4(r0,r1,r2,r3,addr) \
    asm volatile("ldmatrix.sync.aligned.m8n8.x4.shared.b16 {%0,%1,%2,%3}, [%4];\n" \
        : "=r"(r0),"=r"(r1),"=r"(r2),"=r"(r3) : "r"(addr))
#define LDSM_X4_T(r0,r1,r2,r3,addr) \
    asm volatile("ldmatrix.sync.aligned.m8n8.x4.trans.shared.b16 {%0,%1,%2,%3}, [%4];\n" \
        : "=r"(r0),"=r"(r1),"=r"(r2),"=r"(r3) : "r"(addr))

__device__ __forceinline__ void mma16816(float* c, uint32_t a0, uint32_t a1,
                                         uint32_t a2, uint32_t a3,
                                         uint32_t b0, uint32_t b1) {
    asm volatile("mma.sync.aligned.m16n8k16.row.col.f32.f16.f16.f32 "
                 "{%0,%1,%2,%3}, {%4,%5,%6,%7}, {%8,%9}, {%0,%1,%2,%3};\n"
                 : "+f"(c[0]), "+f"(c[1]), "+f"(c[2]), "+f"(c[3])
                 : "r"(a0), "r"(a1), "r"(a2), "r"(a3), "r"(b0), "r"(b1));
}
__device__ __forceinline__ void mma16816_h(uint32_t* c, uint32_t a0, uint32_t a1,
                                           uint32_t a2, uint32_t a3,
                                           uint32_t b0, uint32_t b1) {
    asm volatile("mma.sync.aligned.m16n8k16.row.col.f16.f16.f16.f16 "
                 "{%0,%1}, {%2,%3,%4,%5}, {%6,%7}, {%0,%1};\n"
                 : "+r"(c[0]), "+r"(c[1])
                 : "r"(a0), "r"(a1), "r"(a2), "r"(a3), "r"(b0), "r"(b1));
}
__device__ __forceinline__ uint32_t ex2_f16x2(uint32_t h) {
    uint32_t p; asm("ex2.approx.f16x2 %0, %1;\n" : "=r"(p) : "r"(h)); return p;
}
__device__ __forceinline__ uint32_t h2pack(float a, float b) {
    __half2 h = __floats2half2_rn(a, b);
    return *reinterpret_cast<uint32_t*>(&h);
}
__device__ __forceinline__ uint32_t hadd2u(uint32_t a, uint32_t b) {
    __half2 r = __hadd2(*reinterpret_cast<__half2*>(&a), *reinterpret_cast<__half2*>(&b));
    return *reinterpret_cast<uint32_t*>(&r);
}
__device__ __forceinline__ uint32_t sw_off(int row, int chunk) {
    return (uint32_t)(row * 128 + ((chunk ^ (row & 7)) << 4));
}

// ---------------- fp32 -> fp16 converts --------------------------------------
__global__ void tohalf_w(const float* __restrict__ Wq, const float* __restrict__ Wk,
                         const float* __restrict__ Wv, const float* __restrict__ Wo)
{
    int j = blockIdx.x * blockDim.x + threadIdx.x;
    int w = j >> 18, idx = j & ((1 << 18) - 1);
    const float* src = w == 0 ? Wq  : w == 1 ? Wk  : w == 2 ? Wv  : Wo;
    __half*      dst = w == 0 ? g_wq : w == 1 ? g_wk : w == 2 ? g_wv : g_wo;
    float4 v = ((const float4*)src)[idx];
    uint2 o; o.x = h2pack(v.x, v.y); o.y = h2pack(v.z, v.w);
    ((uint2*)dst)[idx] = o;
}
__global__ void tohalf_x(const float* __restrict__ x, int half)
{
    int i = blockIdx.x * blockDim.x + threadIdx.x;
    int idx = i + half * (1 << 20);
    float4 v = ((const float4*)x)[idx];
    uint2 o; o.x = h2pack(v.x, v.y); o.y = h2pack(v.z, v.w);
    ((uint2*)g_x)[idx] = o;
}

// ---------------- GEMM: C = A @ W^T + b (R12 config: 128x128, occ 2) --------
#define GSTAGE  32768
#define GSTAGES 3

template<int MODE>
__global__ __launch_bounds__(128, 2) void gemm_kernel(
    const float* __restrict__ b0p, const float* __restrict__ b1p,
    const float* __restrict__ b2p, float* __restrict__ Cout, int yoff)
{
    extern __shared__ char smem[];
    const uint32_t su = smem_u32(smem);
    const int tid = threadIdx.x, lane = tid & 31, wid = tid >> 5;
    const int wm = wid >> 1, wn = wid & 1;
    const int m0 = (blockIdx.y + yoff) * 128;

    const __half* A = (MODE == 0) ? g_x : g_a;
    const __half* W; const float* bias; int which, nloc0;
    if (MODE == 0) {
        which = blockIdx.x >> 3;
        nloc0 = (blockIdx.x & 7) * 128;
        W    = which == 0 ? g_wq : (which == 1 ? g_wk : g_wv);
        bias = which == 0 ? b0p  : (which == 1 ? b1p  : b2p);
    } else {
        which = 0; nloc0 = blockIdx.x * 128;
        W = g_wo; bias = b0p;
    }

    float acc[4][8][4];
#pragma unroll
    for (int mt = 0; mt < 4; mt++)
#pragma unroll
        for (int nt = 0; nt < 8; nt++)
#pragma unroll
            for (int r = 0; r < 4; r++) acc[mt][nt][r] = 0.f;

    auto load_stage = [&](int st, int k0) {
        uint32_t sb = su + st * GSTAGE;
#pragma unroll
        for (int i = 0; i < 8; i++) {
            int id = tid + i * 128;
            int row = id >> 3, ch = id & 7;
            uint32_t off = sw_off(row, ch);
            CP16(sb + off,         A + (size_t)(m0 + row) * HID + k0 + ch * 8);
            CP16(sb + 16384 + off, W + (size_t)(nloc0 + row) * HID + k0 + ch * 8);
        }
        CP_COMMIT();
    };

    load_stage(0, 0);
    load_stage(1, 64);
    CP_WAIT1();
    __syncthreads();

    for (int it = 0; it < 16; it++) {
        uint32_t sA = su + (it % GSTAGES) * GSTAGE;
        uint32_t sB = sA + 16384;

#pragma unroll
        for (int ks = 0; ks < 4; ks++) {
            uint32_t a[4][4];
#pragma unroll
            for (int mt = 0; mt < 4; mt++) {
                int row = wm * 64 + mt * 16 + (lane & 15);
                int ch  = ks * 2 + (lane >> 4);
                LDSM_X4(a[mt][0], a[mt][1], a[mt][2], a[mt][3], sA + sw_off(row, ch));
            }
            uint32_t b[4][4];
#pragma unroll
            for (int pr = 0; pr < 4; pr++) {
                int row = wn * 64 + pr * 16 + (lane & 7) + 8 * (lane >> 4);
                int ch  = ks * 2 + ((lane >> 3) & 1);
                LDSM_X4(b[pr][0], b[pr][1], b[pr][2], b[pr][3], sB + sw_off(row, ch));
            }
#pragma unroll
            for (int mt = 0; mt < 4; mt++)
#pragma unroll
                for (int nt = 0; nt < 8; nt++) {
                    int pr = nt >> 1, ix = (nt & 1) * 2;
                    mma16816(acc[mt][nt], a[mt][0], a[mt][1], a[mt][2], a[mt][3],
                             b[pr][ix], b[pr][ix + 1]);
                }
        }

        if (it + 2 < 16) load_stage((it + 2) % GSTAGES, (it + 2) * 64);
        else             CP_COMMIT();
        CP_WAIT1();
        __syncthreads();
    }

    const int gr = lane >> 2, gc2 = (lane & 3) * 2;
#pragma unroll
    for (int mt = 0; mt < 4; mt++) {
#pragma unroll
        for (int nt = 0; nt < 8; nt++) {
            int c = nloc0 + wn * 64 + nt * 8 + gc2;
            float bi0 = bias[c], bi1 = bias[c + 1];
#pragma unroll
            for (int r = 0; r < 2; r++) {
                int m = m0 + wm * 64 + mt * 16 + gr + r * 8;
                float v0 = acc[mt][nt][r * 2 + 0] + bi0;
                float v1 = acc[mt][nt][r * 2 + 1] + bi1;
                if (MODE == 0) {
                    if (which == 0) { v0 *= QSCALE; v1 *= QSCALE; }
                    __half* dst = which == 0 ? g_q : (which == 1 ? g_k : g_v);
                    int b = m >> 11, s = m & (S_ - 1);
                    int h = c >> 6, d = c & 63;
                    __half2 hv = __floats2half2_rn(v0, v1);
                    *(__half2*)&dst[(((size_t)(b * H_ + h)) * S_ + s) * D_ + d] = hv;
                } else {
                    float2 f2 = make_float2(v0, v1);
                    *(float2*)&Cout[(size_t)m * HID + c] = f2;
                }
            }
        }
    }
}

// ---------------- flash attention (unchanged) --------------------------------
#define ASTAGE 16384

__global__ __launch_bounds__(256, 2) void attn_kernel(int bhoff)
{
    extern __shared__ char smem[];
    const uint32_t su  = smem_u32(smem);
    const uint32_t sKV = su + 16384;
    const int tid = threadIdx.x, lane = tid & 31, wid = tid >> 5;
    const int qt = blockIdx.x, bh = blockIdx.y + bhoff;
    const size_t qbase  = ((size_t)bh * S_ + qt * 128) * D_;
    const size_t kvbase = (size_t)bh * S_ * D_;

#pragma unroll
    for (int i = 0; i < 4; i++) {
        int id = tid + i * 256;
        int row = id >> 3, ch = id & 7;
        CP16(su + sw_off(row, ch), g_q + qbase + (size_t)row * 64 + ch * 8);
    }
    CP_COMMIT();

    auto load_kv = [&](int st, int kt) {
        const __half* kp = g_k + kvbase + (size_t)kt * 64 * 64;
        const __half* vp = g_v + kvbase + (size_t)kt * 64 * 64;
        uint32_t sb = sKV + st * ASTAGE;
#pragma unroll
        for (int i = 0; i < 2; i++) {
            int id = tid + i * 256;
            int row = id >> 3, ch = id & 7;
            uint32_t off = sw_off(row, ch);
            CP16(sb + off,        kp + (size_t)row * 64 + ch * 8);
            CP16(sb + 8192 + off, vp + (size_t)row * 64 + ch * 8);
        }
        CP_COMMIT();
    };
    load_kv(0, 0);
    load_kv(1, 1);

    CP_WAIT1();
    __syncthreads();

    uint32_t qf[4][4];
#pragma unroll
    for (int ks = 0; ks < 4; ks++) {
        int row = wid * 16 + (lane & 15);
        int ch  = ks * 2 + (lane >> 4);
        LDSM_X4(qf[ks][0], qf[ks][1], qf[ks][2], qf[ks][3], su + sw_off(row, ch));
    }

    float oa[8][4];
#pragma unroll
    for (int nt = 0; nt < 8; nt++)
#pragma unroll
        for (int r = 0; r < 4; r++) oa[nt][r] = 0.f;
    float rs0 = 0.f, rs1 = 0.f;

    for (int kt = 0; kt < 32; kt++) {
        const uint32_t kb = sKV + (kt % 3) * ASTAGE;
        const uint32_t vb = kb + 8192;

        uint32_t sch[8][2];
#pragma unroll
        for (int nt = 0; nt < 8; nt++) { sch[nt][0] = 0u; sch[nt][1] = 0u; }
#pragma unroll
        for (int ks = 0; ks < 4; ks++) {
#pragma unroll
            for (int pr = 0; pr < 4; pr++) {
                uint32_t bk0, bk1, bk2, bk3;
                int row = pr * 16 + (lane & 7) + 8 * (lane >> 4);
                int ch  = ks * 2 + ((lane >> 3) & 1);
                LDSM_X4(bk0, bk1, bk2, bk3, kb + sw_off(row, ch));
                mma16816_h(sch[pr * 2 + 0], qf[ks][0], qf[ks][1], qf[ks][2], qf[ks][3], bk0, bk1);
                mma16816_h(sch[pr * 2 + 1], qf[ks][0], qf[ks][1], qf[ks][2], qf[ks][3], bk2, bk3);
            }
        }

        uint32_t pa[4][4];
        uint32_t hs0 = 0, hs1 = 0;
#pragma unroll
        for (int ks = 0; ks < 4; ks++) {
            uint32_t p00 = ex2_f16x2(sch[2 * ks + 0][0]);
            uint32_t p01 = ex2_f16x2(sch[2 * ks + 0][1]);
            uint32_t p10 = ex2_f16x2(sch[2 * ks + 1][0]);
            uint32_t p11 = ex2_f16x2(sch[2 * ks + 1][1]);
            pa[ks][0] = p00; pa[ks][1] = p01; pa[ks][2] = p10; pa[ks][3] = p11;
            hs0 = hadd2u(hadd2u(hs0, p00), p10);
            hs1 = hadd2u(hadd2u(hs1, p01), p11);
        }
        {
            float2 f0 = __half22float2(*reinterpret_cast<__half2*>(&hs0));
            float2 f1 = __half22float2(*reinterpret_cast<__half2*>(&hs1));
            rs0 += f0.x + f0.y;
            rs1 += f1.x + f1.y;
        }

#pragma unroll
        for (int ks = 0; ks < 4; ks++) {
#pragma unroll
            for (int pr = 0; pr < 4; pr++) {
                uint32_t bv0, bv1, bv2, bv3;
                int row = ks * 16 + (lane & 15);
                int ch  = pr * 2 + (lane >> 4);
                LDSM_X4_T(bv0, bv1, bv2, bv3, vb + sw_off(row, ch));
                mma16816(oa[pr * 2 + 0], pa[ks][0], pa[ks][1], pa[ks][2], pa[ks][3], bv0, bv1);
                mma16816(oa[pr * 2 + 1], pa[ks][0], pa[ks][1], pa[ks][2], pa[ks][3], bv2, bv3);
            }
        }

        if (kt + 2 < 32) load_kv((kt + 2) % 3, kt + 2);
        else             CP_COMMIT();
        CP_WAIT1();
        __syncthreads();
    }

    rs0 += __shfl_xor_sync(0xffffffffu, rs0, 1);
    rs0 += __shfl_xor_sync(0xffffffffu, rs0, 2);
    rs1 += __shfl_xor_sync(0xffffffffu, rs1, 1);
    rs1 += __shfl_xor_sync(0xffffffffu, rs1, 2);

    const int b = bh >> 4, h = bh & 15;
    const float inv0 = 1.f / rs0, inv1 = 1.f / rs1;
    const int gr = lane >> 2, gc2 = (lane & 3) * 2;
#pragma unroll
    for (int nt = 0; nt < 8; nt++) {
        int d = nt * 8 + gc2;
        int col = h * 64 + d;
#pragma unroll
        for (int r = 0; r < 2; r++) {
            int sG = qt * 128 + wid * 16 + gr + r * 8;
            size_t idx = ((size_t)(b * S_ + sG)) * HID + col;
            float v0 = oa[nt][r * 2 + 0] * (r ? inv1 : inv0);
            float v1 = oa[nt][r * 2 + 1] * (r ? inv1 : inv0);
            *(__half2*)&g_a[idx] = __floats2half2_rn(v0, v1);
        }
    }
}

// ---------------- streams/events: created at program load -------------------
struct StreamBundle {
    cudaStream_t s1 = nullptr, s2 = nullptr;
    cudaEvent_t  eFork = nullptr, eW = nullptr, eX0 = nullptr, eQh = nullptr, eJoin = nullptr;
    bool ok = false;
    StreamBundle() { init(); }
    void init() {
        if (ok) return;
        if (cudaStreamCreateWithFlags(&s1, cudaStreamNonBlocking) != cudaSuccess) return;
        if (cudaStreamCreateWithFlags(&s2, cudaStreamNonBlocking) != cudaSuccess) return;
        if (cudaEventCreateWithFlags(&eFork, cudaEventDisableTiming) != cudaSuccess) return;
        if (cudaEventCreateWithFlags(&eW,    cudaEventDisableTiming) != cudaSuccess) return;
        if (cudaEventCreateWithFlags(&eX0,   cudaEventDisableTiming) != cudaSuccess) return;
        if (cudaEventCreateWithFlags(&eQh,   cudaEventDisableTiming) != cudaSuccess) return;
        if (cudaEventCreateWithFlags(&eJoin, cudaEventDisableTiming) != cudaSuccess) return;
        ok = true;
    }
};
static StreamBundle g_sb;

// ---------------------------------------------------------------------------
extern "C" void kernel_launch(void* const* d_in, const int* in_sizes, int n_in,
                              void* d_out, int out_size)
{
    const float* x  = (const float*)d_in[0];
    const float* Wq = (const float*)d_in[1];
    const float* bq = (const float*)d_in[2];
    const float* Wk = (const float*)d_in[3];
    const float* bk = (const float*)d_in[4];
    const float* Wv = (const float*)d_in[5];
    const float* bv = (const float*)d_in[6];
    const float* Wo = (const float*)d_in[7];
    const float* bo = (const float*)d_in[8];
    float* out = (float*)d_out;

    static bool attr_done = false;
    if (!attr_done) {
        cudaFuncSetAttribute(gemm_kernel<0>, cudaFuncAttributeMaxDynamicSharedMemorySize, GSTAGES * GSTAGE);
        cudaFuncSetAttribute(gemm_kernel<1>, cudaFuncAttributeMaxDynamicSharedMemorySize, GSTAGES * GSTAGE);
        cudaFuncSetAttribute(attn_kernel,    cudaFuncAttributeMaxDynamicSharedMemorySize, 65536);
        attr_done = true;
    }
    g_sb.init();

    const cudaStream_t s0 = 0;
    const bool fork = g_sb.ok;
    const cudaStream_t s1 = fork ? g_sb.s1 : s0;
    const cudaStream_t s2 = fork ? g_sb.s2 : s0;

    if (fork) {
        cudaEventRecord(g_sb.eFork, s0);
        cudaStreamWaitEvent(s1, g_sb.eFork, 0);
        cudaStreamWaitEvent(s2, g_sb.eFork, 0);
    }

    // weights on s0; x halves on s1/s2 — all three concurrent
    tohalf_w<<<(4 * (1 << 18)) / 256, 256, 0, s0>>>(Wq, Wk, Wv, Wo);
    if (fork) cudaEventRecord(g_sb.eW, s0);

    tohalf_x<<<(1 << 20) / 256, 256, 0, s2>>>(x, 0);   // chain-0's half on s2
    if (fork) {
        cudaEventRecord(g_sb.eX0, s2);
        cudaStreamWaitEvent(s0, g_sb.eX0, 0);          // chain 0 (s0) needs x half 0
    }

    tohalf_x<<<(1 << 20) / 256, 256, 0, s1>>>(x, 1);   // chain-1's half on s1
    if (fork) cudaStreamWaitEvent(s1, g_sb.eW, 0);     // chain 1 needs weights

    // chain 1 (batches 2,3) on s1 — QKV split in two halves; event after 1st
    {
        dim3 g1a(24, 16);
        gemm_kernel<0><<<g1a, 128, GSTAGES * GSTAGE, s1>>>(bq, bk, bv, nullptr, 32);
        if (fork) cudaEventRecord(g_sb.eQh, s1);
        dim3 g1b(24, 16);
        gemm_kernel<0><<<g1b, 128, GSTAGES * GSTAGE, s1>>>(bq, bk, bv, nullptr, 48);
        dim3 g2(16, 32);
        attn_kernel<<<g2, 256, 65536, s1>>>(32);
        dim3 g3(8, 32);
        gemm_kernel<1><<<g3, 128, GSTAGES * GSTAGE, s1>>>(bo, nullptr, nullptr, out, 32);
    }

    // chain 0 (batches 0,1) on s0 — staggered: waits for half of chain-1's QKV,
    // keeping the machine full (chain-1's 2nd half runs) while desynchronizing
    // the chains' phases by ~half a QKV so later tails/phases mix.
    {
        if (fork) cudaStreamWaitEvent(s0, g_sb.eQh, 0);
        dim3 g1(24, 32);
        gemm_kernel<0><<<g1, 128, GSTAGES * GSTAGE, s0>>>(bq, bk, bv, nullptr, 0);
        dim3 g2(16, 32);
        attn_kernel<<<g2, 256, 65536, s0>>>(0);
        dim3 g3(8, 32);
        gemm_kernel<1><<<g3, 128, GSTAGES * GSTAGE, s0>>>(bo, nullptr, nullptr, out, 0);
    }

    if (fork) {
        cudaEventRecord(g_sb.eJoin, s1);
        cudaStreamWaitEvent(s0, g_sb.eJoin, 0);
    }
}

// round 15
// speedup vs baseline: 1.0306x; 1.0300x over previous
#include <cuda_runtime.h>
#include <cuda_fp16.h>
#include <stdint.h>

#define B_   4
#define S_   2048
#define H_   16
#define D_   64
#define HID  1024
#define M_   (B_*S_)            // 8192
#define QSCALE 0.1803368801111f // 0.125 * log2(e)  (folded into q)

// ---------------- scratch (device globals; no cudaMalloc allowed) ----------
__device__ __align__(16) __half g_x[(size_t)M_*HID];
__device__ __align__(16) __half g_wq[HID*HID], g_wk[HID*HID], g_wv[HID*HID], g_wo[HID*HID];
__device__ __align__(16) __half g_q[(size_t)M_*HID], g_k[(size_t)M_*HID], g_v[(size_t)M_*HID]; // [bh][s][d]
__device__ __align__(16) __half g_a[(size_t)M_*HID];  // attn out [b*S+s][h*64+d]

// ---------------- PTX helpers ----------------------------------------------
__device__ __forceinline__ uint32_t smem_u32(const void* p) {
    return (uint32_t)__cvta_generic_to_shared(p);
}
#define CP16(dst, src) asm volatile("cp.async.cg.shared.global [%0], [%1], 16;\n" :: "r"(dst), "l"(src))
#define CP_COMMIT()    asm volatile("cp.async.commit_group;\n")
#define CP_WAIT1()     asm volatile("cp.async.wait_group 1;\n")

#define LDSM_X4(r0,r1,r2,r3,addr) \
    asm volatile("ldmatrix.sync.aligned.m8n8.x4.shared.b16 {%0,%1,%2,%3}, [%4];\n" \
        : "=r"(r0),"=r"(r1),"=r"(r2),"=r"(r3) : "r"(addr))
#define LDSM_X4_T(r0,r1,r2,r3,addr) \
    asm volatile("ldmatrix.sync.aligned.m8n8.x4.trans.shared.b16 {%0,%1,%2,%3}, [%4];\n" \
        : "=r"(r0),"=r"(r1),"=r"(r2),"=r"(r3) : "r"(addr))

__device__ __forceinline__ void mma16816(float* c, uint32_t a0, uint32_t a1,
                                         uint32_t a2, uint32_t a3,
                                         uint32_t b0, uint32_t b1) {
    asm volatile("mma.sync.aligned.m16n8k16.row.col.f32.f16.f16.f32 "
                 "{%0,%1,%2,%3}, {%4,%5,%6,%7}, {%8,%9}, {%0,%1,%2,%3};\n"
                 : "+f"(c[0]), "+f"(c[1]), "+f"(c[2]), "+f"(c[3])
                 : "r"(a0), "r"(a1), "r"(a2), "r"(a3), "r"(b0), "r"(b1));
}
__device__ __forceinline__ void mma16816_h(uint32_t* c, uint32_t a0, uint32_t a1,
                                           uint32_t a2, uint32_t a3,
                                           uint32_t b0, uint32_t b1) {
    asm volatile("mma.sync.aligned.m16n8k16.row.col.f16.f16.f16.f16 "
                 "{%0,%1}, {%2,%3,%4,%5}, {%6,%7}, {%0,%1};\n"
                 : "+r"(c[0]), "+r"(c[1])
                 : "r"(a0), "r"(a1), "r"(a2), "r"(a3), "r"(b0), "r"(b1));
}
__device__ __forceinline__ uint32_t ex2_f16x2(uint32_t h) {
    uint32_t p; asm("ex2.approx.f16x2 %0, %1;\n" : "=r"(p) : "r"(h)); return p;
}
__device__ __forceinline__ uint32_t h2pack(float a, float b) {
    __half2 h = __floats2half2_rn(a, b);
    return *reinterpret_cast<uint32_t*>(&h);
}
__device__ __forceinline__ uint32_t hadd2u(uint32_t a, uint32_t b) {
    __half2 r = __hadd2(*reinterpret_cast<__half2*>(&a), *reinterpret_cast<__half2*>(&b));
    return *reinterpret_cast<uint32_t*>(&r);
}
__device__ __forceinline__ uint32_t sw_off(int row, int chunk) {
    return (uint32_t)(row * 128 + ((chunk ^ (row & 7)) << 4));
}

// ---------------- fp32 -> fp16 converts --------------------------------------
__global__ void tohalf_w(const float* __restrict__ Wq, const float* __restrict__ Wk,
                         const float* __restrict__ Wv, const float* __restrict__ Wo)
{
    int j = blockIdx.x * blockDim.x + threadIdx.x;
    int w = j >> 18, idx = j & ((1 << 18) - 1);
    const float* src = w == 0 ? Wq  : w == 1 ? Wk  : w == 2 ? Wv  : Wo;
    __half*      dst = w == 0 ? g_wq : w == 1 ? g_wk : w == 2 ? g_wv : g_wo;
    float4 v = ((const float4*)src)[idx];
    uint2 o; o.x = h2pack(v.x, v.y); o.y = h2pack(v.z, v.w);
    ((uint2*)dst)[idx] = o;
}
__global__ void tohalf_x(const float* __restrict__ x, int half)
{
    int i = blockIdx.x * blockDim.x + threadIdx.x;
    int idx = i + half * (1 << 20);
    float4 v = ((const float4*)x)[idx];
    uint2 o; o.x = h2pack(v.x, v.y); o.y = h2pack(v.z, v.w);
    ((uint2*)g_x)[idx] = o;
}

// ---------------- GEMM: C = A @ W^T + b (128x128 tile, 4 warps, occ 2) ------
#define GSTAGE  32768
#define GSTAGES 3

template<int MODE>
__global__ __launch_bounds__(128, 2) void gemm_kernel(
    const float* __restrict__ b0p, const float* __restrict__ b1p,
    const float* __restrict__ b2p, float* __restrict__ Cout, int yoff)
{
    extern __shared__ char smem[];
    const uint32_t su = smem_u32(smem);
    const int tid = threadIdx.x, lane = tid & 31, wid = tid >> 5;
    const int wm = wid >> 1, wn = wid & 1;
    const int m0 = (blockIdx.y + yoff) * 128;

    const __half* A = (MODE == 0) ? g_x : g_a;
    const __half* W; const float* bias; int which, nloc0;
    if (MODE == 0) {
        which = blockIdx.x >> 3;
        nloc0 = (blockIdx.x & 7) * 128;
        W    = which == 0 ? g_wq : (which == 1 ? g_wk : g_wv);
        bias = which == 0 ? b0p  : (which == 1 ? b1p  : b2p);
    } else {
        which = 0; nloc0 = blockIdx.x * 128;
        W = g_wo; bias = b0p;
    }

    float acc[4][8][4];
#pragma unroll
    for (int mt = 0; mt < 4; mt++)
#pragma unroll
        for (int nt = 0; nt < 8; nt++)
#pragma unroll
            for (int r = 0; r < 4; r++) acc[mt][nt][r] = 0.f;

    auto load_stage = [&](int st, int k0) {
        uint32_t sb = su + st * GSTAGE;
#pragma unroll
        for (int i = 0; i < 8; i++) {
            int id = tid + i * 128;
            int row = id >> 3, ch = id & 7;
            uint32_t off = sw_off(row, ch);
            CP16(sb + off,         A + (size_t)(m0 + row) * HID + k0 + ch * 8);
            CP16(sb + 16384 + off, W + (size_t)(nloc0 + row) * HID + k0 + ch * 8);
        }
        CP_COMMIT();
    };

    load_stage(0, 0);
    load_stage(1, 64);
    CP_WAIT1();
    __syncthreads();

    for (int it = 0; it < 16; it++) {
        uint32_t sA = su + (it % GSTAGES) * GSTAGE;
        uint32_t sB = sA + 16384;

#pragma unroll
        for (int ks = 0; ks < 4; ks++) {
            uint32_t a[4][4];
#pragma unroll
            for (int mt = 0; mt < 4; mt++) {
                int row = wm * 64 + mt * 16 + (lane & 15);
                int ch  = ks * 2 + (lane >> 4);
                LDSM_X4(a[mt][0], a[mt][1], a[mt][2], a[mt][3], sA + sw_off(row, ch));
            }
            uint32_t b[4][4];
#pragma unroll
            for (int pr = 0; pr < 4; pr++) {
                int row = wn * 64 + pr * 16 + (lane & 7) + 8 * (lane >> 4);
                int ch  = ks * 2 + ((lane >> 3) & 1);
                LDSM_X4(b[pr][0], b[pr][1], b[pr][2], b[pr][3], sB + sw_off(row, ch));
            }
#pragma unroll
            for (int mt = 0; mt < 4; mt++)
#pragma unroll
                for (int nt = 0; nt < 8; nt++) {
                    int pr = nt >> 1, ix = (nt & 1) * 2;
                    mma16816(acc[mt][nt], a[mt][0], a[mt][1], a[mt][2], a[mt][3],
                             b[pr][ix], b[pr][ix + 1]);
                }
        }

        if (it + 2 < 16) load_stage((it + 2) % GSTAGES, (it + 2) * 64);
        else             CP_COMMIT();
        CP_WAIT1();
        __syncthreads();
    }

    const int gr = lane >> 2, gc2 = (lane & 3) * 2;
#pragma unroll
    for (int mt = 0; mt < 4; mt++) {
#pragma unroll
        for (int nt = 0; nt < 8; nt++) {
            int c = nloc0 + wn * 64 + nt * 8 + gc2;
            float bi0 = bias[c], bi1 = bias[c + 1];
#pragma unroll
            for (int r = 0; r < 2; r++) {
                int m = m0 + wm * 64 + mt * 16 + gr + r * 8;
                float v0 = acc[mt][nt][r * 2 + 0] + bi0;
                float v1 = acc[mt][nt][r * 2 + 1] + bi1;
                if (MODE == 0) {
                    if (which == 0) { v0 *= QSCALE; v1 *= QSCALE; }
                    __half* dst = which == 0 ? g_q : (which == 1 ? g_k : g_v);
                    int b = m >> 11, s = m & (S_ - 1);
                    int h = c >> 6, d = c & 63;
                    __half2 hv = __floats2half2_rn(v0, v1);
                    *(__half2*)&dst[(((size_t)(b * H_ + h)) * S_ + s) * D_ + d] = hv;
                } else {
                    float2 f2 = make_float2(v0, v1);
                    *(float2*)&Cout[(size_t)m * HID + c] = f2;
                }
            }
        }
    }
}

// ---------------- flash attention ---------------------------------------------
#define ASTAGE 16384

__global__ __launch_bounds__(256, 2) void attn_kernel(int bhoff)
{
    extern __shared__ char smem[];
    const uint32_t su  = smem_u32(smem);
    const uint32_t sKV = su + 16384;
    const int tid = threadIdx.x, lane = tid & 31, wid = tid >> 5;
    const int qt = blockIdx.x, bh = blockIdx.y + bhoff;
    const size_t qbase  = ((size_t)bh * S_ + qt * 128) * D_;
    const size_t kvbase = (size_t)bh * S_ * D_;

#pragma unroll
    for (int i = 0; i < 4; i++) {
        int id = tid + i * 256;
        int row = id >> 3, ch = id & 7;
        CP16(su + sw_off(row, ch), g_q + qbase + (size_t)row * 64 + ch * 8);
    }
    CP_COMMIT();

    auto load_kv = [&](int st, int kt) {
        const __half* kp = g_k + kvbase + (size_t)kt * 64 * 64;
        const __half* vp = g_v + kvbase + (size_t)kt * 64 * 64;
        uint32_t sb = sKV + st * ASTAGE;
#pragma unroll
        for (int i = 0; i < 2; i++) {
            int id = tid + i * 256;
            int row = id >> 3, ch = id & 7;
            uint32_t off = sw_off(row, ch);
            CP16(sb + off,        kp + (size_t)row * 64 + ch * 8);
            CP16(sb + 8192 + off, vp + (size_t)row * 64 + ch * 8);
        }
        CP_COMMIT();
    };
    load_kv(0, 0);
    load_kv(1, 1);

    CP_WAIT1();
    __syncthreads();

    uint32_t qf[4][4];
#pragma unroll
    for (int ks = 0; ks < 4; ks++) {
        int row = wid * 16 + (lane & 15);
        int ch  = ks * 2 + (lane >> 4);
        LDSM_X4(qf[ks][0], qf[ks][1], qf[ks][2], qf[ks][3], su + sw_off(row, ch));
    }

    float oa[8][4];
#pragma unroll
    for (int nt = 0; nt < 8; nt++)
#pragma unroll
        for (int r = 0; r < 4; r++) oa[nt][r] = 0.f;
    float rs0 = 0.f, rs1 = 0.f;

    for (int kt = 0; kt < 32; kt++) {
        const uint32_t kb = sKV + (kt % 3) * ASTAGE;
        const uint32_t vb = kb + 8192;

        uint32_t sch[8][2];
#pragma unroll
        for (int nt = 0; nt < 8; nt++) { sch[nt][0] = 0u; sch[nt][1] = 0u; }
#pragma unroll
        for (int ks = 0; ks < 4; ks++) {
#pragma unroll
            for (int pr = 0; pr < 4; pr++) {
                uint32_t bk0, bk1, bk2, bk3;
                int row = pr * 16 + (lane & 7) + 8 * (lane >> 4);
                int ch  = ks * 2 + ((lane >> 3) & 1);
                LDSM_X4(bk0, bk1, bk2, bk3, kb + sw_off(row, ch));
                mma16816_h(sch[pr * 2 + 0], qf[ks][0], qf[ks][1], qf[ks][2], qf[ks][3], bk0, bk1);
                mma16816_h(sch[pr * 2 + 1], qf[ks][0], qf[ks][1], qf[ks][2], qf[ks][3], bk2, bk3);
            }
        }

        uint32_t pa[4][4];
        uint32_t hs0 = 0, hs1 = 0;
#pragma unroll
        for (int ks = 0; ks < 4; ks++) {
            uint32_t p00 = ex2_f16x2(sch[2 * ks + 0][0]);
            uint32_t p01 = ex2_f16x2(sch[2 * ks + 0][1]);
            uint32_t p10 = ex2_f16x2(sch[2 * ks + 1][0]);
            uint32_t p11 = ex2_f16x2(sch[2 * ks + 1][1]);
            pa[ks][0] = p00; pa[ks][1] = p01; pa[ks][2] = p10; pa[ks][3] = p11;
            hs0 = hadd2u(hadd2u(hs0, p00), p10);
            hs1 = hadd2u(hadd2u(hs1, p01), p11);
        }
        {
            float2 f0 = __half22float2(*reinterpret_cast<__half2*>(&hs0));
            float2 f1 = __half22float2(*reinterpret_cast<__half2*>(&hs1));
            rs0 += f0.x + f0.y;
            rs1 += f1.x + f1.y;
        }

#pragma unroll
        for (int ks = 0; ks < 4; ks++) {
#pragma unroll
            for (int pr = 0; pr < 4; pr++) {
                uint32_t bv0, bv1, bv2, bv3;
                int row = ks * 16 + (lane & 15);
                int ch  = pr * 2 + (lane >> 4);
                LDSM_X4_T(bv0, bv1, bv2, bv3, vb + sw_off(row, ch));
                mma16816(oa[pr * 2 + 0], pa[ks][0], pa[ks][1], pa[ks][2], pa[ks][3], bv0, bv1);
                mma16816(oa[pr * 2 + 1], pa[ks][0], pa[ks][1], pa[ks][2], pa[ks][3], bv2, bv3);
            }
        }

        if (kt + 2 < 32) load_kv((kt + 2) % 3, kt + 2);
        else             CP_COMMIT();
        CP_WAIT1();
        __syncthreads();
    }

    rs0 += __shfl_xor_sync(0xffffffffu, rs0, 1);
    rs0 += __shfl_xor_sync(0xffffffffu, rs0, 2);
    rs1 += __shfl_xor_sync(0xffffffffu, rs1, 1);
    rs1 += __shfl_xor_sync(0xffffffffu, rs1, 2);

    const int b = bh >> 4, h = bh & 15;
    const float inv0 = 1.f / rs0, inv1 = 1.f / rs1;
    const int gr = lane >> 2, gc2 = (lane & 3) * 2;
#pragma unroll
    for (int nt = 0; nt < 8; nt++) {
        int d = nt * 8 + gc2;
        int col = h * 64 + d;
#pragma unroll
        for (int r = 0; r < 2; r++) {
            int sG = qt * 128 + wid * 16 + gr + r * 8;
            size_t idx = ((size_t)(b * S_ + sG)) * HID + col;
            float v0 = oa[nt][r * 2 + 0] * (r ? inv1 : inv0);
            float v1 = oa[nt][r * 2 + 1] * (r ? inv1 : inv0);
            *(__half2*)&g_a[idx] = __floats2half2_rn(v0, v1);
        }
    }
}

// ---------------- streams/events: created at program load -------------------
struct StreamBundle {
    cudaStream_t s1 = nullptr, s2 = nullptr;
    cudaEvent_t  eFork = nullptr, eW = nullptr, eX0 = nullptr, eJoin = nullptr;
    bool ok = false;
    StreamBundle() { init(); }
    void init() {
        if (ok) return;
        if (cudaStreamCreateWithFlags(&s1, cudaStreamNonBlocking) != cudaSuccess) return;
        if (cudaStreamCreateWithFlags(&s2, cudaStreamNonBlocking) != cudaSuccess) return;
        if (cudaEventCreateWithFlags(&eFork, cudaEventDisableTiming) != cudaSuccess) return;
        if (cudaEventCreateWithFlags(&eW,    cudaEventDisableTiming) != cudaSuccess) return;
        if (cudaEventCreateWithFlags(&eX0,   cudaEventDisableTiming) != cudaSuccess) return;
        if (cudaEventCreateWithFlags(&eJoin, cudaEventDisableTiming) != cudaSuccess) return;
        ok = true;
    }
};
static StreamBundle g_sb;

// ---------------------------------------------------------------------------
extern "C" void kernel_launch(void* const* d_in, const int* in_sizes, int n_in,
                              void* d_out, int out_size)
{
    const float* x  = (const float*)d_in[0];
    const float* Wq = (const float*)d_in[1];
    const float* bq = (const float*)d_in[2];
    const float* Wk = (const float*)d_in[3];
    const float* bk = (const float*)d_in[4];
    const float* Wv = (const float*)d_in[5];
    const float* bv = (const float*)d_in[6];
    const float* Wo = (const float*)d_in[7];
    const float* bo = (const float*)d_in[8];
    float* out = (float*)d_out;

    static bool attr_done = false;
    if (!attr_done) {
        cudaFuncSetAttribute(gemm_kernel<0>, cudaFuncAttributeMaxDynamicSharedMemorySize, GSTAGES * GSTAGE);
        cudaFuncSetAttribute(gemm_kernel<1>, cudaFuncAttributeMaxDynamicSharedMemorySize, GSTAGES * GSTAGE);
        cudaFuncSetAttribute(attn_kernel,    cudaFuncAttributeMaxDynamicSharedMemorySize, 65536);
        attr_done = true;
    }
    g_sb.init();

    const cudaStream_t s0 = 0;
    const bool fork = g_sb.ok;
    const cudaStream_t s1 = fork ? g_sb.s1 : s0;
    const cudaStream_t s2 = fork ? g_sb.s2 : s0;

    // fork immediately: the three converts are mutually independent
    if (fork) {
        cudaEventRecord(g_sb.eFork, s0);
        cudaStreamWaitEvent(s1, g_sb.eFork, 0);
        cudaStreamWaitEvent(s2, g_sb.eFork, 0);
    }

    // weights on s0; x halves on s1/s2 — all three concurrent
    tohalf_w<<<(4 * (1 << 18)) / 256, 256, 0, s0>>>(Wq, Wk, Wv, Wo);
    if (fork) cudaEventRecord(g_sb.eW, s0);

    tohalf_x<<<(1 << 20) / 256, 256, 0, s2>>>(x, 0);   // chain-0's half on s2
    if (fork) {
        cudaEventRecord(g_sb.eX0, s2);
        cudaStreamWaitEvent(s0, g_sb.eX0, 0);          // chain 0 (s0) needs x half 0
    }

    tohalf_x<<<(1 << 20) / 256, 256, 0, s1>>>(x, 1);   // chain-1's half on s1
    if (fork) cudaStreamWaitEvent(s1, g_sb.eW, 0);     // chain 1 needs weights

    // chain 1 (batches 2,3) on s1
    {
        dim3 g1(24, 32);
        gemm_kernel<0><<<g1, 128, GSTAGES * GSTAGE, s1>>>(bq, bk, bv, nullptr, 32);
        dim3 g2(16, 32);
        attn_kernel<<<g2, 256, 65536, s1>>>(32);
        dim3 g3(8, 32);
        gemm_kernel<1><<<g3, 128, GSTAGES * GSTAGE, s1>>>(bo, nullptr, nullptr, out, 32);
    }

    // chain 0 (batches 0,1) on s0 (weights by stream order, x0 via eX0)
    {
        dim3 g1(24, 32);
        gemm_kernel<0><<<g1, 128, GSTAGES * GSTAGE, s0>>>(bq, bk, bv, nullptr, 0);
        dim3 g2(16, 32);
        attn_kernel<<<g2, 256, 65536, s0>>>(0);
        dim3 g3(8, 32);
        gemm_kernel<1><<<g3, 128, GSTAGES * GSTAGE, s0>>>(bo, nullptr, nullptr, out, 0);
    }

    if (fork) {
        cudaEventRecord(g_sb.eJoin, s1);
        cudaStreamWaitEvent(s0, g_sb.eJoin, 0);
    }
}

// round 16
// speedup vs baseline: 1.0325x; 1.0019x over previous
#include <cuda_runtime.h>
#include <cuda_fp16.h>
#include <stdint.h>

#define B_   4
#define S_   2048
#define H_   16
#define D_   64
#define HID  1024
#define M_   (B_*S_)            // 8192
#define QSCALE 0.1803368801111f // 0.125 * log2(e)  (folded into q)

// ---------------- scratch (device globals; no cudaMalloc allowed) ----------
__device__ __align__(16) __half g_x[(size_t)M_*HID];
__device__ __align__(16) __half g_wq[HID*HID], g_wk[HID*HID], g_wv[HID*HID], g_wo[HID*HID];
__device__ __align__(16) __half g_q[(size_t)M_*HID], g_k[(size_t)M_*HID], g_v[(size_t)M_*HID]; // [bh][s][d]
__device__ __align__(16) __half g_a[(size_t)M_*HID];  // attn out [b*S+s][h*64+d]

// ---------------- PTX helpers ----------------------------------------------
__device__ __forceinline__ uint32_t smem_u32(const void* p) {
    return (uint32_t)__cvta_generic_to_shared(p);
}
#define CP16(dst, src) asm volatile("cp.async.cg.shared.global [%0], [%1], 16;\n" :: "r"(dst), "l"(src))
#define CP_COMMIT()    asm volatile("cp.async.commit_group;\n")
#define CP_WAIT1()     asm volatile("cp.async.wait_group 1;\n")

#define LDSM_X4(r0,r1,r2,r3,addr) \
    asm volatile("ldmatrix.sync.aligned.m8n8.x4.shared.b16 {%0,%1,%2,%3}, [%4];\n" \
        : "=r"(r0),"=r"(r1),"=r"(r2),"=r"(r3) : "r"(addr))
#define LDSM_X4_T(r0,r1,r2,r3,addr) \
    asm volatile("ldmatrix.sync.aligned.m8n8.x4.trans.shared.b16 {%0,%1,%2,%3}, [%4];\n" \
        : "=r"(r0),"=r"(r1),"=r"(r2),"=r"(r3) : "r"(addr))

__device__ __forceinline__ void mma16816(float* c, uint32_t a0, uint32_t a1,
                                         uint32_t a2, uint32_t a3,
                                         uint32_t b0, uint32_t b1) {
    asm volatile("mma.sync.aligned.m16n8k16.row.col.f32.f16.f16.f32 "
                 "{%0,%1,%2,%3}, {%4,%5,%6,%7}, {%8,%9}, {%0,%1,%2,%3};\n"
                 : "+f"(c[0]), "+f"(c[1]), "+f"(c[2]), "+f"(c[3])
                 : "r"(a0), "r"(a1), "r"(a2), "r"(a3), "r"(b0), "r"(b1));
}
__device__ __forceinline__ void mma16816_h(uint32_t* c, uint32_t a0, uint32_t a1,
                                           uint32_t a2, uint32_t a3,
                                           uint32_t b0, uint32_t b1) {
    asm volatile("mma.sync.aligned.m16n8k16.row.col.f16.f16.f16.f16 "
                 "{%0,%1}, {%2,%3,%4,%5}, {%6,%7}, {%0,%1};\n"
                 : "+r"(c[0]), "+r"(c[1])
                 : "r"(a0), "r"(a1), "r"(a2), "r"(a3), "r"(b0), "r"(b1));
}
__device__ __forceinline__ uint32_t ex2_f16x2(uint32_t h) {
    uint32_t p; asm("ex2.approx.f16x2 %0, %1;\n" : "=r"(p) : "r"(h)); return p;
}
__device__ __forceinline__ uint32_t h2pack(float a, float b) {
    __half2 h = __floats2half2_rn(a, b);
    return *reinterpret_cast<uint32_t*>(&h);
}
__device__ __forceinline__ uint32_t hadd2u(uint32_t a, uint32_t b) {
    __half2 r = __hadd2(*reinterpret_cast<__half2*>(&a), *reinterpret_cast<__half2*>(&b));
    return *reinterpret_cast<uint32_t*>(&r);
}
__device__ __forceinline__ uint32_t sw_off(int row, int chunk) {
    return (uint32_t)(row * 128 + ((chunk ^ (row & 7)) << 4));
}

// ---------------- fp32 -> fp16 converts (ILP 2: two independent float4) -----
__global__ void tohalf_w(const float* __restrict__ Wq, const float* __restrict__ Wk,
                         const float* __restrict__ Wv, const float* __restrict__ Wo)
{
    // 4 weights x 2^18 float4 total; each thread converts 2 float4 within one W
    int t = blockIdx.x * blockDim.x + threadIdx.x;   // 0 .. 4*2^17-1
    int w = t >> 17, base = (t & ((1 << 17) - 1)) * 2;
    const float* src = w == 0 ? Wq  : w == 1 ? Wk  : w == 2 ? Wv  : Wo;
    __half*      dst = w == 0 ? g_wq : w == 1 ? g_wk : w == 2 ? g_wv : g_wo;
    float4 v0 = ((const float4*)src)[base];
    float4 v1 = ((const float4*)src)[base + 1];
    uint4 o;
    o.x = h2pack(v0.x, v0.y); o.y = h2pack(v0.z, v0.w);
    o.z = h2pack(v1.x, v1.y); o.w = h2pack(v1.z, v1.w);
    ((uint4*)dst)[base >> 1] = o;
}
// x half: 2^20 float4 per half; 2 independent float4 per thread
__global__ void tohalf_x(const float* __restrict__ x, int half)
{
    int t = blockIdx.x * blockDim.x + threadIdx.x;   // 0 .. 2^19-1
    int base = t * 2 + half * (1 << 20);
    float4 v0 = ((const float4*)x)[base];
    float4 v1 = ((const float4*)x)[base + 1];
    uint4 o;
    o.x = h2pack(v0.x, v0.y); o.y = h2pack(v0.z, v0.w);
    o.z = h2pack(v1.x, v1.y); o.w = h2pack(v1.z, v1.w);
    ((uint4*)g_x)[base >> 1] = o;
}

// ---------------- GEMM: C = A @ W^T + b (128x128 tile, 4 warps, occ 2) ------
#define GSTAGE  32768
#define GSTAGES 3

template<int MODE>
__global__ __launch_bounds__(128, 2) void gemm_kernel(
    const float* __restrict__ b0p, const float* __restrict__ b1p,
    const float* __restrict__ b2p, float* __restrict__ Cout, int yoff)
{
    extern __shared__ char smem[];
    const uint32_t su = smem_u32(smem);
    const int tid = threadIdx.x, lane = tid & 31, wid = tid >> 5;
    const int wm = wid >> 1, wn = wid & 1;
    const int m0 = (blockIdx.y + yoff) * 128;

    const __half* A = (MODE == 0) ? g_x : g_a;
    const __half* W; const float* bias; int which, nloc0;
    if (MODE == 0) {
        which = blockIdx.x >> 3;
        nloc0 = (blockIdx.x & 7) * 128;
        W    = which == 0 ? g_wq : (which == 1 ? g_wk : g_wv);
        bias = which == 0 ? b0p  : (which == 1 ? b1p  : b2p);
    } else {
        which = 0; nloc0 = blockIdx.x * 128;
        W = g_wo; bias = b0p;
    }

    float acc[4][8][4];
#pragma unroll
    for (int mt = 0; mt < 4; mt++)
#pragma unroll
        for (int nt = 0; nt < 8; nt++)
#pragma unroll
            for (int r = 0; r < 4; r++) acc[mt][nt][r] = 0.f;

    auto load_stage = [&](int st, int k0) {
        uint32_t sb = su + st * GSTAGE;
#pragma unroll
        for (int i = 0; i < 8; i++) {
            int id = tid + i * 128;
            int row = id >> 3, ch = id & 7;
            uint32_t off = sw_off(row, ch);
            CP16(sb + off,         A + (size_t)(m0 + row) * HID + k0 + ch * 8);
            CP16(sb + 16384 + off, W + (size_t)(nloc0 + row) * HID + k0 + ch * 8);
        }
        CP_COMMIT();
    };

    load_stage(0, 0);
    load_stage(1, 64);
    CP_WAIT1();
    __syncthreads();

    for (int it = 0; it < 16; it++) {
        uint32_t sA = su + (it % GSTAGES) * GSTAGE;
        uint32_t sB = sA + 16384;

#pragma unroll
        for (int ks = 0; ks < 4; ks++) {
            uint32_t a[4][4];
#pragma unroll
            for (int mt = 0; mt < 4; mt++) {
                int row = wm * 64 + mt * 16 + (lane & 15);
                int ch  = ks * 2 + (lane >> 4);
                LDSM_X4(a[mt][0], a[mt][1], a[mt][2], a[mt][3], sA + sw_off(row, ch));
            }
            uint32_t b[4][4];
#pragma unroll
            for (int pr = 0; pr < 4; pr++) {
                int row = wn * 64 + pr * 16 + (lane & 7) + 8 * (lane >> 4);
                int ch  = ks * 2 + ((lane >> 3) & 1);
                LDSM_X4(b[pr][0], b[pr][1], b[pr][2], b[pr][3], sB + sw_off(row, ch));
            }
#pragma unroll
            for (int mt = 0; mt < 4; mt++)
#pragma unroll
                for (int nt = 0; nt < 8; nt++) {
                    int pr = nt >> 1, ix = (nt & 1) * 2;
                    mma16816(acc[mt][nt], a[mt][0], a[mt][1], a[mt][2], a[mt][3],
                             b[pr][ix], b[pr][ix + 1]);
                }
        }

        if (it + 2 < 16) load_stage((it + 2) % GSTAGES, (it + 2) * 64);
        else             CP_COMMIT();
        CP_WAIT1();
        __syncthreads();
    }

    const int gr = lane >> 2, gc2 = (lane & 3) * 2;
#pragma unroll
    for (int mt = 0; mt < 4; mt++) {
#pragma unroll
        for (int nt = 0; nt < 8; nt++) {
            int c = nloc0 + wn * 64 + nt * 8 + gc2;
            float bi0 = bias[c], bi1 = bias[c + 1];
#pragma unroll
            for (int r = 0; r < 2; r++) {
                int m = m0 + wm * 64 + mt * 16 + gr + r * 8;
                float v0 = acc[mt][nt][r * 2 + 0] + bi0;
                float v1 = acc[mt][nt][r * 2 + 1] + bi1;
                if (MODE == 0) {
                    if (which == 0) { v0 *= QSCALE; v1 *= QSCALE; }
                    __half* dst = which == 0 ? g_q : (which == 1 ? g_k : g_v);
                    int b = m >> 11, s = m & (S_ - 1);
                    int h = c >> 6, d = c & 63;
                    __half2 hv = __floats2half2_rn(v0, v1);
                    *(__half2*)&dst[(((size_t)(b * H_ + h)) * S_ + s) * D_ + d] = hv;
                } else {
                    float2 f2 = make_float2(v0, v1);
                    *(float2*)&Cout[(size_t)m * HID + c] = f2;
                }
            }
        }
    }
}

// ---------------- flash attention ---------------------------------------------
#define ASTAGE 16384

__global__ __launch_bounds__(256, 2) void attn_kernel(int bhoff)
{
    extern __shared__ char smem[];
    const uint32_t su  = smem_u32(smem);
    const uint32_t sKV = su + 16384;
    const int tid = threadIdx.x, lane = tid & 31, wid = tid >> 5;
    const int qt = blockIdx.x, bh = blockIdx.y + bhoff;
    const size_t qbase  = ((size_t)bh * S_ + qt * 128) * D_;
    const size_t kvbase = (size_t)bh * S_ * D_;

#pragma unroll
    for (int i = 0; i < 4; i++) {
        int id = tid + i * 256;
        int row = id >> 3, ch = id & 7;
        CP16(su + sw_off(row, ch), g_q + qbase + (size_t)row * 64 + ch * 8);
    }
    CP_COMMIT();

    auto load_kv = [&](int st, int kt) {
        const __half* kp = g_k + kvbase + (size_t)kt * 64 * 64;
        const __half* vp = g_v + kvbase + (size_t)kt * 64 * 64;
        uint32_t sb = sKV + st * ASTAGE;
#pragma unroll
        for (int i = 0; i < 2; i++) {
            int id = tid + i * 256;
            int row = id >> 3, ch = id & 7;
            uint32_t off = sw_off(row, ch);
            CP16(sb + off,        kp + (size_t)row * 64 + ch * 8);
            CP16(sb + 8192 + off, vp + (size_t)row * 64 + ch * 8);
        }
        CP_COMMIT();
    };
    load_kv(0, 0);
    load_kv(1, 1);

    CP_WAIT1();
    __syncthreads();

    uint32_t qf[4][4];
#pragma unroll
    for (int ks = 0; ks < 4; ks++) {
        int row = wid * 16 + (lane & 15);
        int ch  = ks * 2 + (lane >> 4);
        LDSM_X4(qf[ks][0], qf[ks][1], qf[ks][2], qf[ks][3], su + sw_off(row, ch));
    }

    float oa[8][4];
#pragma unroll
    for (int nt = 0; nt < 8; nt++)
#pragma unroll
        for (int r = 0; r < 4; r++) oa[nt][r] = 0.f;
    float rs0 = 0.f, rs1 = 0.f;

    for (int kt = 0; kt < 32; kt++) {
        const uint32_t kb = sKV + (kt % 3) * ASTAGE;
        const uint32_t vb = kb + 8192;

        uint32_t sch[8][2];
#pragma unroll
        for (int nt = 0; nt < 8; nt++) { sch[nt][0] = 0u; sch[nt][1] = 0u; }
#pragma unroll
        for (int ks = 0; ks < 4; ks++) {
#pragma unroll
            for (int pr = 0; pr < 4; pr++) {
                uint32_t bk0, bk1, bk2, bk3;
                int row = pr * 16 + (lane & 7) + 8 * (lane >> 4);
                int ch  = ks * 2 + ((lane >> 3) & 1);
                LDSM_X4(bk0, bk1, bk2, bk3, kb + sw_off(row, ch));
                mma16816_h(sch[pr * 2 + 0], qf[ks][0], qf[ks][1], qf[ks][2], qf[ks][3], bk0, bk1);
                mma16816_h(sch[pr * 2 + 1], qf[ks][0], qf[ks][1], qf[ks][2], qf[ks][3], bk2, bk3);
            }
        }

        uint32_t pa[4][4];
        uint32_t hs0 = 0, hs1 = 0;
#pragma unroll
        for (int ks = 0; ks < 4; ks++) {
            uint32_t p00 = ex2_f16x2(sch[2 * ks + 0][0]);
            uint32_t p01 = ex2_f16x2(sch[2 * ks + 0][1]);
            uint32_t p10 = ex2_f16x2(sch[2 * ks + 1][0]);
            uint32_t p11 = ex2_f16x2(sch[2 * ks + 1][1]);
            pa[ks][0] = p00; pa[ks][1] = p01; pa[ks][2] = p10; pa[ks][3] = p11;
            hs0 = hadd2u(hadd2u(hs0, p00), p10);
            hs1 = hadd2u(hadd2u(hs1, p01), p11);
        }
        {
            float2 f0 = __half22float2(*reinterpret_cast<__half2*>(&hs0));
            float2 f1 = __half22float2(*reinterpret_cast<__half2*>(&hs1));
            rs0 += f0.x + f0.y;
            rs1 += f1.x + f1.y;
        }

#pragma unroll
        for (int ks = 0; ks < 4; ks++) {
#pragma unroll
            for (int pr = 0; pr < 4; pr++) {
                uint32_t bv0, bv1, bv2, bv3;
                int row = ks * 16 + (lane & 15);
                int ch  = pr * 2 + (lane >> 4);
                LDSM_X4_T(bv0, bv1, bv2, bv3, vb + sw_off(row, ch));
                mma16816(oa[pr * 2 + 0], pa[ks][0], pa[ks][1], pa[ks][2], pa[ks][3], bv0, bv1);
                mma16816(oa[pr * 2 + 1], pa[ks][0], pa[ks][1], pa[ks][2], pa[ks][3], bv2, bv3);
            }
        }

        if (kt + 2 < 32) load_kv((kt + 2) % 3, kt + 2);
        else             CP_COMMIT();
        CP_WAIT1();
        __syncthreads();
    }

    rs0 += __shfl_xor_sync(0xffffffffu, rs0, 1);
    rs0 += __shfl_xor_sync(0xffffffffu, rs0, 2);
    rs1 += __shfl_xor_sync(0xffffffffu, rs1, 1);
    rs1 += __shfl_xor_sync(0xffffffffu, rs1, 2);

    const int b = bh >> 4, h = bh & 15;
    const float inv0 = 1.f / rs0, inv1 = 1.f / rs1;
    const int gr = lane >> 2, gc2 = (lane & 3) * 2;
#pragma unroll
    for (int nt = 0; nt < 8; nt++) {
        int d = nt * 8 + gc2;
        int col = h * 64 + d;
#pragma unroll
        for (int r = 0; r < 2; r++) {
            int sG = qt * 128 + wid * 16 + gr + r * 8;
            size_t idx = ((size_t)(b * S_ + sG)) * HID + col;
            float v0 = oa[nt][r * 2 + 0] * (r ? inv1 : inv0);
            float v1 = oa[nt][r * 2 + 1] * (r ? inv1 : inv0);
            *(__half2*)&g_a[idx] = __floats2half2_rn(v0, v1);
        }
    }
}

// ---------------- streams/events: created at program load -------------------
struct StreamBundle {
    cudaStream_t s1 = nullptr, s2 = nullptr;
    cudaEvent_t  eFork = nullptr, eW = nullptr, eX0 = nullptr, eJoin = nullptr;
    bool ok = false;
    StreamBundle() { init(); }
    void init() {
        if (ok) return;
        if (cudaStreamCreateWithFlags(&s1, cudaStreamNonBlocking) != cudaSuccess) return;
        if (cudaStreamCreateWithFlags(&s2, cudaStreamNonBlocking) != cudaSuccess) return;
        if (cudaEventCreateWithFlags(&eFork, cudaEventDisableTiming) != cudaSuccess) return;
        if (cudaEventCreateWithFlags(&eW,    cudaEventDisableTiming) != cudaSuccess) return;
        if (cudaEventCreateWithFlags(&eX0,   cudaEventDisableTiming) != cudaSuccess) return;
        if (cudaEventCreateWithFlags(&eJoin, cudaEventDisableTiming) != cudaSuccess) return;
        ok = true;
    }
};
static StreamBundle g_sb;

// ---------------------------------------------------------------------------
extern "C" void kernel_launch(void* const* d_in, const int* in_sizes, int n_in,
                              void* d_out, int out_size)
{
    const float* x  = (const float*)d_in[0];
    const float* Wq = (const float*)d_in[1];
    const float* bq = (const float*)d_in[2];
    const float* Wk = (const float*)d_in[3];
    const float* bk = (const float*)d_in[4];
    const float* Wv = (const float*)d_in[5];
    const float* bv = (const float*)d_in[6];
    const float* Wo = (const float*)d_in[7];
    const float* bo = (const float*)d_in[8];
    float* out = (float*)d_out;

    static bool attr_done = false;
    if (!attr_done) {
        cudaFuncSetAttribute(gemm_kernel<0>, cudaFuncAttributeMaxDynamicSharedMemorySize, GSTAGES * GSTAGE);
        cudaFuncSetAttribute(gemm_kernel<1>, cudaFuncAttributeMaxDynamicSharedMemorySize, GSTAGES * GSTAGE);
        cudaFuncSetAttribute(attn_kernel,    cudaFuncAttributeMaxDynamicSharedMemorySize, 65536);
        attr_done = true;
    }
    g_sb.init();

    const cudaStream_t s0 = 0;
    const bool fork = g_sb.ok;
    const cudaStream_t s1 = fork ? g_sb.s1 : s0;
    const cudaStream_t s2 = fork ? g_sb.s2 : s0;

    // fork immediately: the three converts are mutually independent
    if (fork) {
        cudaEventRecord(g_sb.eFork, s0);
        cudaStreamWaitEvent(s1, g_sb.eFork, 0);
        cudaStreamWaitEvent(s2, g_sb.eFork, 0);
    }

    // weights on s0; x halves on s1/s2 — all three concurrent (ILP-2 converts)
    tohalf_w<<<(4 * (1 << 17)) / 256, 256, 0, s0>>>(Wq, Wk, Wv, Wo);
    if (fork) cudaEventRecord(g_sb.eW, s0);

    tohalf_x<<<(1 << 19) / 256, 256, 0, s2>>>(x, 0);   // chain-0's half on s2
    if (fork) {
        cudaEventRecord(g_sb.eX0, s2);
        cudaStreamWaitEvent(s0, g_sb.eX0, 0);          // chain 0 (s0) needs x half 0
    }

    tohalf_x<<<(1 << 19) / 256, 256, 0, s1>>>(x, 1);   // chain-1's half on s1
    if (fork) cudaStreamWaitEvent(s1, g_sb.eW, 0);     // chain 1 needs weights

    // chain 1 (batches 2,3) on s1
    {
        dim3 g1(24, 32);
        gemm_kernel<0><<<g1, 128, GSTAGES * GSTAGE, s1>>>(bq, bk, bv, nullptr, 32);
        dim3 g2(16, 32);
        attn_kernel<<<g2, 256, 65536, s1>>>(32);
        dim3 g3(8, 32);
        gemm_kernel<1><<<g3, 128, GSTAGES * GSTAGE, s1>>>(bo, nullptr, nullptr, out, 32);
    }

    // chain 0 (batches 0,1) on s0 (weights by stream order, x0 via eX0)
    {
        dim3 g1(24, 32);
        gemm_kernel<0><<<g1, 128, GSTAGES * GSTAGE, s0>>>(bq, bk, bv, nullptr, 0);
        dim3 g2(16, 32);
        attn_kernel<<<g2, 256, 65536, s0>>>(0);
        dim3 g3(8, 32);
        gemm_kernel<1><<<g3, 128, GSTAGES * GSTAGE, s0>>>(bo, nullptr, nullptr, out, 0);
    }

    if (fork) {
        cudaEventRecord(g_sb.eJoin, s1);
        cudaStreamWaitEvent(s0, g_sb.eJoin, 0);
    }
}

// round 17
// speedup vs baseline: 1.0368x; 1.0041x over previous
#include <cuda_runtime.h>
#include <cuda_fp16.h>
#include <stdint.h>

#define B_   4
#define S_   2048
#define H_   16
#define D_   64
#define HID  1024
#define M_   (B_*S_)            // 8192
#define QSCALE 0.1803368801111f // 0.125 * log2(e)  (folded into q)

// ---------------- scratch (device globals; no cudaMalloc allowed) ----------
__device__ __align__(16) __half g_x[(size_t)M_*HID];
__device__ __align__(16) __half g_wq[HID*HID], g_wk[HID*HID], g_wv[HID*HID], g_wo[HID*HID];
__device__ __align__(16) __half g_q[(size_t)M_*HID], g_k[(size_t)M_*HID], g_v[(size_t)M_*HID]; // [bh][s][d]
__device__ __align__(16) __half g_a[(size_t)M_*HID];  // attn out [b*S+s][h*64+d]

// ---------------- PTX helpers ----------------------------------------------
__device__ __forceinline__ uint32_t smem_u32(const void* p) {
    return (uint32_t)__cvta_generic_to_shared(p);
}
#define CP16(dst, src) asm volatile("cp.async.cg.shared.global [%0], [%1], 16;\n" :: "r"(dst), "l"(src))
#define CP_COMMIT()    asm volatile("cp.async.commit_group;\n")
#define CP_WAIT1()     asm volatile("cp.async.wait_group 1;\n")

#define LDSM_X4(r0,r1,r2,r3,addr) \
    asm volatile("ldmatrix.sync.aligned.m8n8.x4.shared.b16 {%0,%1,%2,%3}, [%4];\n" \
        : "=r"(r0),"=r"(r1),"=r"(r2),"=r"(r3) : "r"(addr))
#define LDSM_X4_T(r0,r1,r2,r3,addr) \
    asm volatile("ldmatrix.sync.aligned.m8n8.x4.trans.shared.b16 {%0,%1,%2,%3}, [%4];\n" \
        : "=r"(r0),"=r"(r1),"=r"(r2),"=r"(r3) : "r"(addr))

__device__ __forceinline__ void mma16816(float* c, uint32_t a0, uint32_t a1,
                                         uint32_t a2, uint32_t a3,
                                         uint32_t b0, uint32_t b1) {
    asm volatile("mma.sync.aligned.m16n8k16.row.col.f32.f16.f16.f32 "
                 "{%0,%1,%2,%3}, {%4,%5,%6,%7}, {%8,%9}, {%0,%1,%2,%3};\n"
                 : "+f"(c[0]), "+f"(c[1]), "+f"(c[2]), "+f"(c[3])
                 : "r"(a0), "r"(a1), "r"(a2), "r"(a3), "r"(b0), "r"(b1));
}
__device__ __forceinline__ void mma16816_h(uint32_t* c, uint32_t a0, uint32_t a1,
                                           uint32_t a2, uint32_t a3,
                                           uint32_t b0, uint32_t b1) {
    asm volatile("mma.sync.aligned.m16n8k16.row.col.f16.f16.f16.f16 "
                 "{%0,%1}, {%2,%3,%4,%5}, {%6,%7}, {%0,%1};\n"
                 : "+r"(c[0]), "+r"(c[1])
                 : "r"(a0), "r"(a1), "r"(a2), "r"(a3), "r"(b0), "r"(b1));
}
__device__ __forceinline__ uint32_t ex2_f16x2(uint32_t h) {
    uint32_t p; asm("ex2.approx.f16x2 %0, %1;\n" : "=r"(p) : "r"(h)); return p;
}
__device__ __forceinline__ uint32_t h2pack(float a, float b) {
    __half2 h = __floats2half2_rn(a, b);
    return *reinterpret_cast<uint32_t*>(&h);
}
__device__ __forceinline__ uint32_t hadd2u(uint32_t a, uint32_t b) {
    __half2 r = __hadd2(*reinterpret_cast<__half2*>(&a), *reinterpret_cast<__half2*>(&b));
    return *reinterpret_cast<uint32_t*>(&r);
}
__device__ __forceinline__ uint32_t sw_off(int row, int chunk) {
    return (uint32_t)(row * 128 + ((chunk ^ (row & 7)) << 4));
}

// ---------------- fp32 -> fp16 converts (ILP 2: two independent float4) -----
__global__ void tohalf_w(const float* __restrict__ Wq, const float* __restrict__ Wk,
                         const float* __restrict__ Wv, const float* __restrict__ Wo)
{
    int t = blockIdx.x * blockDim.x + threadIdx.x;   // 0 .. 4*2^17-1
    int w = t >> 17, base = (t & ((1 << 17) - 1)) * 2;
    const float* src = w == 0 ? Wq  : w == 1 ? Wk  : w == 2 ? Wv  : Wo;
    __half*      dst = w == 0 ? g_wq : w == 1 ? g_wk : w == 2 ? g_wv : g_wo;
    float4 v0 = ((const float4*)src)[base];
    float4 v1 = ((const float4*)src)[base + 1];
    uint4 o;
    o.x = h2pack(v0.x, v0.y); o.y = h2pack(v0.z, v0.w);
    o.z = h2pack(v1.x, v1.y); o.w = h2pack(v1.z, v1.w);
    ((uint4*)dst)[base >> 1] = o;
}
__global__ void tohalf_x(const float* __restrict__ x, int half)
{
    int t = blockIdx.x * blockDim.x + threadIdx.x;   // 0 .. 2^19-1
    int base = t * 2 + half * (1 << 20);
    float4 v0 = ((const float4*)x)[base];
    float4 v1 = ((const float4*)x)[base + 1];
    uint4 o;
    o.x = h2pack(v0.x, v0.y); o.y = h2pack(v0.z, v0.w);
    o.z = h2pack(v1.x, v1.y); o.w = h2pack(v1.z, v1.w);
    ((uint4*)g_x)[base >> 1] = o;
}

// ---------------- GEMM: C = A @ W^T + b (128x128 tile, 4 warps, occ 2) ------
#define GSTAGE  32768
#define GSTAGES 3

template<int MODE>
__global__ __launch_bounds__(128, 2) void gemm_kernel(
    const float* __restrict__ b0p, const float* __restrict__ b1p,
    const float* __restrict__ b2p, float* __restrict__ Cout, int yoff)
{
    extern __shared__ char smem[];
    const uint32_t su = smem_u32(smem);
    const int tid = threadIdx.x, lane = tid & 31, wid = tid >> 5;
    const int wm = wid >> 1, wn = wid & 1;
    const int m0 = (blockIdx.y + yoff) * 128;

    const __half* A = (MODE == 0) ? g_x : g_a;
    const __half* W; const float* bias; int which, nloc0;
    if (MODE == 0) {
        which = blockIdx.x >> 3;
        nloc0 = (blockIdx.x & 7) * 128;
        W    = which == 0 ? g_wq : (which == 1 ? g_wk : g_wv);
        bias = which == 0 ? b0p  : (which == 1 ? b1p  : b2p);
    } else {
        which = 0; nloc0 = blockIdx.x * 128;
        W = g_wo; bias = b0p;
    }

    float acc[4][8][4];
#pragma unroll
    for (int mt = 0; mt < 4; mt++)
#pragma unroll
        for (int nt = 0; nt < 8; nt++)
#pragma unroll
            for (int r = 0; r < 4; r++) acc[mt][nt][r] = 0.f;

    auto load_stage = [&](int st, int k0) {
        uint32_t sb = su + st * GSTAGE;
#pragma unroll
        for (int i = 0; i < 8; i++) {
            int id = tid + i * 128;
            int row = id >> 3, ch = id & 7;
            uint32_t off = sw_off(row, ch);
            CP16(sb + off,         A + (size_t)(m0 + row) * HID + k0 + ch * 8);
            CP16(sb + 16384 + off, W + (size_t)(nloc0 + row) * HID + k0 + ch * 8);
        }
        CP_COMMIT();
    };

    load_stage(0, 0);
    load_stage(1, 64);
    CP_WAIT1();
    __syncthreads();

    for (int it = 0; it < 16; it++) {
        uint32_t sA = su + (it % GSTAGES) * GSTAGE;
        uint32_t sB = sA + 16384;

#pragma unroll
        for (int ks = 0; ks < 4; ks++) {
            uint32_t a[4][4];
#pragma unroll
            for (int mt = 0; mt < 4; mt++) {
                int row = wm * 64 + mt * 16 + (lane & 15);
                int ch  = ks * 2 + (lane >> 4);
                LDSM_X4(a[mt][0], a[mt][1], a[mt][2], a[mt][3], sA + sw_off(row, ch));
            }
            uint32_t b[4][4];
#pragma unroll
            for (int pr = 0; pr < 4; pr++) {
                int row = wn * 64 + pr * 16 + (lane & 7) + 8 * (lane >> 4);
                int ch  = ks * 2 + ((lane >> 3) & 1);
                LDSM_X4(b[pr][0], b[pr][1], b[pr][2], b[pr][3], sB + sw_off(row, ch));
            }
#pragma unroll
            for (int mt = 0; mt < 4; mt++)
#pragma unroll
                for (int nt = 0; nt < 8; nt++) {
                    int pr = nt >> 1, ix = (nt & 1) * 2;
                    mma16816(acc[mt][nt], a[mt][0], a[mt][1], a[mt][2], a[mt][3],
                             b[pr][ix], b[pr][ix + 1]);
                }
        }

        if (it + 2 < 16) load_stage((it + 2) % GSTAGES, (it + 2) * 64);
        else             CP_COMMIT();
        CP_WAIT1();
        __syncthreads();
    }

    const int gr = lane >> 2, gc2 = (lane & 3) * 2;
#pragma unroll
    for (int mt = 0; mt < 4; mt++) {
#pragma unroll
        for (int nt = 0; nt < 8; nt++) {
            int c = nloc0 + wn * 64 + nt * 8 + gc2;
            float bi0 = bias[c], bi1 = bias[c + 1];
#pragma unroll
            for (int r = 0; r < 2; r++) {
                int m = m0 + wm * 64 + mt * 16 + gr + r * 8;
                float v0 = acc[mt][nt][r * 2 + 0] + bi0;
                float v1 = acc[mt][nt][r * 2 + 1] + bi1;
                if (MODE == 0) {
                    if (which == 0) { v0 *= QSCALE; v1 *= QSCALE; }
                    __half* dst = which == 0 ? g_q : (which == 1 ? g_k : g_v);
                    int b = m >> 11, s = m & (S_ - 1);
                    int h = c >> 6, d = c & 63;
                    __half2 hv = __floats2half2_rn(v0, v1);
                    *(__half2*)&dst[(((size_t)(b * H_ + h)) * S_ + s) * D_ + d] = hv;
                } else {
                    float2 f2 = make_float2(v0, v1);
                    *(float2*)&Cout[(size_t)m * HID + c] = f2;
                }
            }
        }
    }
}

// ---------------- flash attention ---------------------------------------------
#define ASTAGE 16384

__global__ __launch_bounds__(256, 2) void attn_kernel(int bhoff)
{
    extern __shared__ char smem[];
    const uint32_t su  = smem_u32(smem);
    const uint32_t sKV = su + 16384;
    const int tid = threadIdx.x, lane = tid & 31, wid = tid >> 5;
    const int qt = blockIdx.x, bh = blockIdx.y + bhoff;
    const size_t qbase  = ((size_t)bh * S_ + qt * 128) * D_;
    const size_t kvbase = (size_t)bh * S_ * D_;

#pragma unroll
    for (int i = 0; i < 4; i++) {
        int id = tid + i * 256;
        int row = id >> 3, ch = id & 7;
        CP16(su + sw_off(row, ch), g_q + qbase + (size_t)row * 64 + ch * 8);
    }
    CP_COMMIT();

    auto load_kv = [&](int st, int kt) {
        const __half* kp = g_k + kvbase + (size_t)kt * 64 * 64;
        const __half* vp = g_v + kvbase + (size_t)kt * 64 * 64;
        uint32_t sb = sKV + st * ASTAGE;
#pragma unroll
        for (int i = 0; i < 2; i++) {
            int id = tid + i * 256;
            int row = id >> 3, ch = id & 7;
            uint32_t off = sw_off(row, ch);
            CP16(sb + off,        kp + (size_t)row * 64 + ch * 8);
            CP16(sb + 8192 + off, vp + (size_t)row * 64 + ch * 8);
        }
        CP_COMMIT();
    };
    load_kv(0, 0);
    load_kv(1, 1);

    CP_WAIT1();
    __syncthreads();

    uint32_t qf[4][4];
#pragma unroll
    for (int ks = 0; ks < 4; ks++) {
        int row = wid * 16 + (lane & 15);
        int ch  = ks * 2 + (lane >> 4);
        LDSM_X4(qf[ks][0], qf[ks][1], qf[ks][2], qf[ks][3], su + sw_off(row, ch));
    }

    float oa[8][4];
#pragma unroll
    for (int nt = 0; nt < 8; nt++)
#pragma unroll
        for (int r = 0; r < 4; r++) oa[nt][r] = 0.f;
    float rs0 = 0.f, rs1 = 0.f;

    for (int kt = 0; kt < 32; kt++) {
        const uint32_t kb = sKV + (kt % 3) * ASTAGE;
        const uint32_t vb = kb + 8192;

        uint32_t sch[8][2];
#pragma unroll
        for (int nt = 0; nt < 8; nt++) { sch[nt][0] = 0u; sch[nt][1] = 0u; }
#pragma unroll
        for (int ks = 0; ks < 4; ks++) {
#pragma unroll
            for (int pr = 0; pr < 4; pr++) {
                uint32_t bk0, bk1, bk2, bk3;
                int row = pr * 16 + (lane & 7) + 8 * (lane >> 4);
                int ch  = ks * 2 + ((lane >> 3) & 1);
                LDSM_X4(bk0, bk1, bk2, bk3, kb + sw_off(row, ch));
                mma16816_h(sch[pr * 2 + 0], qf[ks][0], qf[ks][1], qf[ks][2], qf[ks][3], bk0, bk1);
                mma16816_h(sch[pr * 2 + 1], qf[ks][0], qf[ks][1], qf[ks][2], qf[ks][3], bk2, bk3);
            }
        }

        uint32_t pa[4][4];
        uint32_t hs0 = 0, hs1 = 0;
#pragma unroll
        for (int ks = 0; ks < 4; ks++) {
            uint32_t p00 = ex2_f16x2(sch[2 * ks + 0][0]);
            uint32_t p01 = ex2_f16x2(sch[2 * ks + 0][1]);
            uint32_t p10 = ex2_f16x2(sch[2 * ks + 1][0]);
            uint32_t p11 = ex2_f16x2(sch[2 * ks + 1][1]);
            pa[ks][0] = p00; pa[ks][1] = p01; pa[ks][2] = p10; pa[ks][3] = p11;
            hs0 = hadd2u(hadd2u(hs0, p00), p10);
            hs1 = hadd2u(hadd2u(hs1, p01), p11);
        }
        {
            float2 f0 = __half22float2(*reinterpret_cast<__half2*>(&hs0));
            float2 f1 = __half22float2(*reinterpret_cast<__half2*>(&hs1));
            rs0 += f0.x + f0.y;
            rs1 += f1.x + f1.y;
        }

#pragma unroll
        for (int ks = 0; ks < 4; ks++) {
#pragma unroll
            for (int pr = 0; pr < 4; pr++) {
                uint32_t bv0, bv1, bv2, bv3;
                int row = ks * 16 + (lane & 15);
                int ch  = pr * 2 + (lane >> 4);
                LDSM_X4_T(bv0, bv1, bv2, bv3, vb + sw_off(row, ch));
                mma16816(oa[pr * 2 + 0], pa[ks][0], pa[ks][1], pa[ks][2], pa[ks][3], bv0, bv1);
                mma16816(oa[pr * 2 + 1], pa[ks][0], pa[ks][1], pa[ks][2], pa[ks][3], bv2, bv3);
            }
        }

        if (kt + 2 < 32) load_kv((kt + 2) % 3, kt + 2);
        else             CP_COMMIT();
        CP_WAIT1();
        __syncthreads();
    }

    rs0 += __shfl_xor_sync(0xffffffffu, rs0, 1);
    rs0 += __shfl_xor_sync(0xffffffffu, rs0, 2);
    rs1 += __shfl_xor_sync(0xffffffffu, rs1, 1);
    rs1 += __shfl_xor_sync(0xffffffffu, rs1, 2);

    const int b = bh >> 4, h = bh & 15;
    const float inv0 = 1.f / rs0, inv1 = 1.f / rs1;
    const int gr = lane >> 2, gc2 = (lane & 3) * 2;
#pragma unroll
    for (int nt = 0; nt < 8; nt++) {
        int d = nt * 8 + gc2;
        int col = h * 64 + d;
#pragma unroll
        for (int r = 0; r < 2; r++) {
            int sG = qt * 128 + wid * 16 + gr + r * 8;
            size_t idx = ((size_t)(b * S_ + sG)) * HID + col;
            float v0 = oa[nt][r * 2 + 0] * (r ? inv1 : inv0);
            float v1 = oa[nt][r * 2 + 1] * (r ? inv1 : inv0);
            *(__half2*)&g_a[idx] = __floats2half2_rn(v0, v1);
        }
    }
}

// ---------------- streams/events: created at program load -------------------
struct StreamBundle {
    cudaStream_t s1 = nullptr, s2 = nullptr;
    cudaEvent_t  eFork = nullptr, eW = nullptr, eX0 = nullptr, eJoin = nullptr;
    bool ok = false;
    StreamBundle() { init(); }
    void init() {
        if (ok) return;
        if (cudaStreamCreateWithFlags(&s1, cudaStreamNonBlocking) != cudaSuccess) return;
        if (cudaStreamCreateWithFlags(&s2, cudaStreamNonBlocking) != cudaSuccess) return;
        if (cudaEventCreateWithFlags(&eFork, cudaEventDisableTiming) != cudaSuccess) return;
        if (cudaEventCreateWithFlags(&eW,    cudaEventDisableTiming) != cudaSuccess) return;
        if (cudaEventCreateWithFlags(&eX0,   cudaEventDisableTiming) != cudaSuccess) return;
        if (cudaEventCreateWithFlags(&eJoin, cudaEventDisableTiming) != cudaSuccess) return;
        ok = true;
    }
};
static StreamBundle g_sb;

// ---------------------------------------------------------------------------
extern "C" void kernel_launch(void* const* d_in, const int* in_sizes, int n_in,
                              void* d_out, int out_size)
{
    const float* x  = (const float*)d_in[0];
    const float* Wq = (const float*)d_in[1];
    const float* bq = (const float*)d_in[2];
    const float* Wk = (const float*)d_in[3];
    const float* bk = (const float*)d_in[4];
    const float* Wv = (const float*)d_in[5];
    const float* bv = (const float*)d_in[6];
    const float* Wo = (const float*)d_in[7];
    const float* bo = (const float*)d_in[8];
    float* out = (float*)d_out;

    static bool attr_done = false;
    if (!attr_done) {
        cudaFuncSetAttribute(gemm_kernel<0>, cudaFuncAttributeMaxDynamicSharedMemorySize, GSTAGES * GSTAGE);
        cudaFuncSetAttribute(gemm_kernel<1>, cudaFuncAttributeMaxDynamicSharedMemorySize, GSTAGES * GSTAGE);
        cudaFuncSetAttribute(attn_kernel,    cudaFuncAttributeMaxDynamicSharedMemorySize, 65536);
        attr_done = true;
    }
    g_sb.init();

    const cudaStream_t s0 = 0;
    const bool fork = g_sb.ok;
    const cudaStream_t s1 = fork ? g_sb.s1 : s0;
    const cudaStream_t s2 = fork ? g_sb.s2 : s0;

    // fork immediately: the three converts are mutually independent
    if (fork) {
        cudaEventRecord(g_sb.eFork, s0);
        cudaStreamWaitEvent(s1, g_sb.eFork, 0);
        cudaStreamWaitEvent(s2, g_sb.eFork, 0);
    }

    // weights on s0; x halves on s1/s2 — all three concurrent
    tohalf_w<<<(4 * (1 << 17)) / 256, 256, 0, s0>>>(Wq, Wk, Wv, Wo);
    if (fork) cudaEventRecord(g_sb.eW, s0);

    tohalf_x<<<(1 << 19) / 256, 256, 0, s2>>>(x, 0);   // chain-0's half on s2
    if (fork) {
        cudaEventRecord(g_sb.eX0, s2);
        cudaStreamWaitEvent(s0, g_sb.eX0, 0);          // chain 0 (s0) needs x half 0
    }

    tohalf_x<<<(1 << 19) / 256, 256, 0, s1>>>(x, 1);   // chain-1's half on s1
    if (fork) cudaStreamWaitEvent(s1, g_sb.eW, 0);     // chain 1 needs weights

    // chain 1 (batches 2,3) on s1
    {
        dim3 g1(24, 32);
        gemm_kernel<0><<<g1, 128, GSTAGES * GSTAGE, s1>>>(bq, bk, bv, nullptr, 32);
        dim3 g2(16, 32);
        attn_kernel<<<g2, 256, 65536, s1>>>(32);
        dim3 g3(8, 32);
        gemm_kernel<1><<<g3, 128, GSTAGES * GSTAGE, s1>>>(bo, nullptr, nullptr, out, 32);
    }

    // chain 0 (batches 0,1) on s0 (weights by stream order, x0 via eX0)
    {
        dim3 g1(24, 32);
        gemm_kernel<0><<<g1, 128, GSTAGES * GSTAGE, s0>>>(bq, bk, bv, nullptr, 0);
        dim3 g2(16, 32);
        attn_kernel<<<g2, 256, 65536, s0>>>(0);
        dim3 g3(8, 32);
        gemm_kernel<1><<<g3, 128, GSTAGES * GSTAGE, s0>>>(bo, nullptr, nullptr, out, 0);
    }

    if (fork) {
        cudaEventRecord(g_sb.eJoin, s1);
        cudaStreamWaitEvent(s0, g_sb.eJoin, 0);
    }
}